// round 3
// baseline (speedup 1.0000x reference)
#include <cuda_runtime.h>
#include <math.h>

#define TOT 65536
#define BGR 128
#define NPG 512
#define NBINS 16

// ---------------- scratch (__device__ globals; zero-init at load) ----------
__device__ float g_deg[TOT];            // zero-maintained
__device__ float g_dis[TOT];
__device__ float g_invdeg[TOT];
__device__ float g_h0[TOT*64];
__device__ float g_agg[TOT*64];         // zero-maintained
__device__ float g_h1[TOT*64];
__device__ float g_af1[TOT*32];
__device__ float g_af2[TOT*32];
__device__ float g_tdot[(size_t)BGR*NPG*NPG];   // 134MB raw dot scratch
__device__ unsigned g_minu[BGR];
__device__ unsigned g_maxu[BGR];
__device__ float g_thr[BGR*15];
__device__ float g_hist[BGR*NBINS];     // slots 1..15 = cumulative counts
__device__ float g_ctx[BGR*32];
__device__ float g_p1[BGR*32];
__device__ float g_p2[BGR*32];

// ---------------- helpers ---------------------------------------------------
__device__ __forceinline__ unsigned f2o(float f){
    unsigned u = __float_as_uint(f);
    return (u & 0x80000000u) ? ~u : (u | 0x80000000u);
}
__device__ __forceinline__ float o2f(unsigned u){
    return __uint_as_float((u & 0x80000000u) ? (u & 0x7fffffffu) : ~u);
}
__device__ __forceinline__ void red_add4(float* p, float4 v){
    asm volatile("red.global.add.v4.f32 [%0], {%1,%2,%3,%4};"
                 :: "l"(p), "f"(v.x), "f"(v.y), "f"(v.z), "f"(v.w) : "memory");
}

// ---------------- degree ----------------------------------------------------
__global__ void k_deg_count(const int* __restrict__ dst, int E){
    int i = blockIdx.x*256 + threadIdx.x;
    if (i < E) atomicAdd(&g_deg[dst[i]], 1.0f);
}
__global__ void k_deg_fin(){
    int i = blockIdx.x*256 + threadIdx.x;
    float d = g_deg[i] + 1.0f;
    g_dis[i]    = rsqrtf(d);
    g_invdeg[i] = 1.0f/d;
    g_deg[i]    = 0.0f;          // restore zero invariant
}

// ---------------- dense GEMM: g_h0 = X @ W  (X: TOT x K, W: K x M) ----------
template<int K, int M>
__global__ void __launch_bounds__(256) k_gemm(const float* __restrict__ Xext,
                                              const float* __restrict__ W,
                                              int use_h1){
    constexpr int R   = 32;
    constexpr int CPT = M/16;
    __shared__ float sX[R*K];
    __shared__ float sW[K*M];
    const float* X = use_h1 ? g_h1 : Xext;
    int row0 = blockIdx.x * R;

    for (int i = threadIdx.x; i < K*M/4; i += 256)
        ((float4*)sW)[i] = ((const float4*)W)[i];
    const float4* Xg = (const float4*)(X + (size_t)row0*K);
    for (int i = threadIdx.x; i < R*K/4; i += 256)
        ((float4*)sX)[i] = Xg[i];
    __syncthreads();

    int tx = threadIdx.x & 15, ty = threadIdx.x >> 4;
    int c0 = tx*CPT, r0 = ty*2;
    float acc0[CPT] = {}, acc1[CPT] = {};

    #pragma unroll
    for (int k = 0; k < K; k += 4){
        float4 xa = *(const float4*)&sX[ r0   *K + k];
        float4 xb = *(const float4*)&sX[(r0+1)*K + k];
        #pragma unroll
        for (int kk = 0; kk < 4; kk++){
            float va = (&xa.x)[kk];
            float vb = (&xb.x)[kk];
            if (CPT == 4){
                float4 wv = *(const float4*)&sW[(k+kk)*M + c0];
                acc0[0] += va*wv.x; acc0[1] += va*wv.y; acc0[2] += va*wv.z; acc0[3] += va*wv.w;
                acc1[0] += vb*wv.x; acc1[1] += vb*wv.y; acc1[2] += vb*wv.z; acc1[3] += vb*wv.w;
            } else {
                float2 wv = *(const float2*)&sW[(k+kk)*M + c0];
                acc0[0] += va*wv.x; acc0[1] += va*wv.y;
                acc1[0] += vb*wv.x; acc1[1] += vb*wv.y;
            }
        }
    }
    float* O0 = &g_h0[(size_t)(row0 + r0    )*M + c0];
    float* O1 = &g_h0[(size_t)(row0 + r0 + 1)*M + c0];
    if (CPT == 4){
        *(float4*)O0 = make_float4(acc0[0],acc0[1],acc0[2],acc0[3]);
        *(float4*)O1 = make_float4(acc1[0],acc1[1],acc1[2],acc1[3]);
    } else {
        *(float2*)O0 = make_float2(acc0[0],acc0[1]);
        *(float2*)O1 = make_float2(acc1[0],acc1[1]);
    }
}

// ---------------- edge scatter: agg[dst] += h0[src]*dis[src] ----------------
template<int F>
__global__ void __launch_bounds__(256) k_scatter(const int* __restrict__ src,
                                                 const int* __restrict__ dst, int E){
    constexpr int G  = F/4;
    constexpr int SH = (F==64) ? 4 : 3;
    int t = blockIdx.x*256 + threadIdx.x;
    int e = t >> SH, j = t & (G-1);
    if (e >= E) return;
    int s = __ldg(src + e), d = __ldg(dst + e);
    float sc = __ldg(&g_dis[s]);
    float4 v = *(const float4*)&g_h0[(size_t)s*F + 4*j];
    red_add4(&g_agg[(size_t)d*F + 4*j],
             make_float4(v.x*sc, v.y*sc, v.z*sc, v.w*sc));
}

// ---------------- finalize: out = [relu](agg*dis + h0*invdeg + b); agg=0 ----
template<int F, bool RELU>
__global__ void __launch_bounds__(256) k_fin(const float* __restrict__ bias, int out_sel){
    constexpr int SH = (F==64) ? 4 : 3;
    int v = blockIdx.x*256 + threadIdx.x;      // float4 index
    int row = v >> SH;
    int f4  = v & ((F/4)-1);
    float4 a = ((float4*)g_agg)[v];
    float4 h = ((const float4*)g_h0)[v];
    float di = g_dis[row], iv = g_invdeg[row];
    float4 bb = ((const float4*)bias)[f4];
    float4 o;
    o.x = a.x*di + h.x*iv + bb.x;
    o.y = a.y*di + h.y*iv + bb.y;
    o.z = a.z*di + h.z*iv + bb.z;
    o.w = a.w*di + h.w*iv + bb.w;
    if (RELU){
        o.x = fmaxf(o.x,0.f); o.y = fmaxf(o.y,0.f);
        o.z = fmaxf(o.z,0.f); o.w = fmaxf(o.w,0.f);
    }
    float* out = (out_sel==0) ? g_h1 : (out_sel==1 ? g_af1 : g_af2);
    ((float4*)out)[v] = o;
    ((float4*)g_agg)[v] = make_float4(0.f,0.f,0.f,0.f);
}

// ---------------- histogram -------------------------------------------------
__global__ void k_hist_init(){
    int t = blockIdx.x*256 + threadIdx.x;
    if (t < BGR){ g_minu[t] = 0xFFFFFFFFu; g_maxu[t] = 0u; }
    if (t < BGR*NBINS) g_hist[t] = 0.f;
}

__global__ void __launch_bounds__(256) k_dot(){
    __shared__ float sA[32*129];
    __shared__ float sB[32*129];
    int b    = blockIdx.x >> 4;
    int tile = blockIdx.x & 15;
    int i0 = (tile >> 2) * 128, j0 = (tile & 3) * 128;
    const float* A  = g_af1 + ((size_t)b*NPG + i0)*32;
    const float* Bp = g_af2 + ((size_t)b*NPG + j0)*32;
    for (int idx = threadIdx.x; idx < 128*32; idx += 256){
        int r = idx >> 5, k = idx & 31;
        sA[k*129 + r] = A[idx];
        sB[k*129 + r] = Bp[idx];
    }
    __syncthreads();
    int tx = threadIdx.x & 15, ty = threadIdx.x >> 4;
    float acc[8][8] = {};
    #pragma unroll
    for (int k = 0; k < 32; k++){
        float av[8], bv[8];
        #pragma unroll
        for (int a=0;a<8;a++) av[a] = sA[k*129 + ty + 16*a];
        #pragma unroll
        for (int c=0;c<8;c++) bv[c] = sB[k*129 + tx + 16*c];
        #pragma unroll
        for (int a=0;a<8;a++)
            #pragma unroll
            for (int c=0;c<8;c++) acc[a][c] += av[a]*bv[c];
    }
    float lmin = acc[0][0], lmax = acc[0][0];
    float* od = g_tdot + ((size_t)b << 18);
    #pragma unroll
    for (int a=0;a<8;a++){
        int i = i0 + ty + 16*a;
        #pragma unroll
        for (int c=0;c<8;c++){
            float v = acc[a][c];
            lmin = fminf(lmin, v); lmax = fmaxf(lmax, v);
            od[(size_t)i*NPG + j0 + tx + 16*c] = v;
        }
    }
    #pragma unroll
    for (int off=16; off; off>>=1){
        lmin = fminf(lmin, __shfl_down_sync(0xffffffffu, lmin, off));
        lmax = fmaxf(lmax, __shfl_down_sync(0xffffffffu, lmax, off));
    }
    __shared__ float wmn[8], wmx[8];
    int w = threadIdx.x >> 5;
    if ((threadIdx.x & 31) == 0){ wmn[w] = lmin; wmx[w] = lmax; }
    __syncthreads();
    if (threadIdx.x == 0){
        float m = wmn[0], M = wmx[0];
        for (int q=1;q<8;q++){ m = fminf(m, wmn[q]); M = fmaxf(M, wmx[q]); }
        atomicMin(&g_minu[b], f2o(m));
        atomicMax(&g_maxu[b], f2o(M));
    }
}

__global__ void k_thr(){
    int b = threadIdx.x;
    if (b >= BGR) return;
    float tmin = o2f(g_minu[b]), tmax = o2f(g_maxu[b]);
    float mn = 1.0f/(1.0f + expf(-tmin));
    float mx = 1.0f/(1.0f + expf(-tmax));
    float rng = (mx > mn) ? (mx - mn) : 1.0f;
    const float PINF = __int_as_float(0x7f800000);
    for (int k = 1; k <= 15; k++){
        float p = mn + rng * (k * (1.0f/16.0f));
        float thr;
        if (p <= 0.0f)      thr = -PINF;
        else if (p >= 1.0f) thr =  PINF;
        else                thr = logf(p / (1.0f - p));
        g_thr[b*15 + k - 1] = thr;
    }
}

__global__ void __launch_bounds__(256) k_bin(){
    int b = blockIdx.y;
    int chunk = blockIdx.x;   // 0..3
    const float4* base = (const float4*)(g_tdot + ((size_t)b << 18))
                         + ((size_t)chunk << 14) + threadIdx.x;
    float thr[15];
    #pragma unroll
    for (int k=0;k<15;k++) thr[k] = g_thr[b*15 + k];
    float c[15] = {};
    for (int it = 0; it < 64; it++){
        float4 v = base[it*256];
        #pragma unroll
        for (int k=0;k<15;k++){
            c[k] += (v.x >= thr[k]) ? 1.0f : 0.0f;
            c[k] += (v.y >= thr[k]) ? 1.0f : 0.0f;
            c[k] += (v.z >= thr[k]) ? 1.0f : 0.0f;
            c[k] += (v.w >= thr[k]) ? 1.0f : 0.0f;
        }
    }
    #pragma unroll
    for (int off=16; off; off>>=1)
        #pragma unroll
        for (int k=0;k<15;k++)
            c[k] += __shfl_down_sync(0xffffffffu, c[k], off);
    if ((threadIdx.x & 31) == 0)
        #pragma unroll
        for (int k=0;k<15;k++)
            atomicAdd(&g_hist[b*NBINS + k + 1], c[k]);
}

// ---------------- attention pooling ----------------------------------------
__global__ void __launch_bounds__(256) k_att1(const float* __restrict__ attW, int sel){
    const float* af = (sel==1) ? g_af1 : g_af2;
    int b = blockIdx.x;
    __shared__ float sm[8*32], smean[32];
    int f = threadIdx.x & 31, grp = threadIdx.x >> 5;
    const float* base = af + (size_t)b*NPG*32;
    float acc = 0.f;
    for (int n = grp; n < NPG; n += 8) acc += base[n*32 + f];
    sm[grp*32 + f] = acc;
    __syncthreads();
    if (threadIdx.x < 32){
        float m = 0.f;
        for (int g=0; g<8; g++) m += sm[g*32 + threadIdx.x];
        smean[threadIdx.x] = m * (1.0f/512.0f);
    }
    __syncthreads();
    if (threadIdx.x < 32){
        int j = threadIdx.x;
        float t = 0.f;
        for (int ff=0; ff<32; ff++) t += smean[ff]*attW[ff*32 + j];
        g_ctx[b*32 + j] = tanhf(t);
    }
}

__global__ void __launch_bounds__(256) k_att2(int sel){
    const float* af = (sel==1) ? g_af1 : g_af2;
    float* gp       = (sel==1) ? g_p1  : g_p2;
    int b = blockIdx.x;
    __shared__ float st[32];
    __shared__ float ssig[NPG];
    __shared__ float sm[8*32];
    if (threadIdx.x < 32) st[threadIdx.x] = g_ctx[b*32 + threadIdx.x];
    __syncthreads();
    const float* base = af + (size_t)b*NPG*32;
    for (int n = threadIdx.x; n < NPG; n += 256){
        float d = 0.f;
        #pragma unroll
        for (int q=0; q<8; q++){
            float4 v = *(const float4*)(base + n*32 + q*4);
            d += v.x*st[q*4] + v.y*st[q*4+1] + v.z*st[q*4+2] + v.w*st[q*4+3];
        }
        ssig[n] = 1.0f/(1.0f + __expf(-d));
    }
    __syncthreads();
    int f = threadIdx.x & 31, grp = threadIdx.x >> 5;
    float acc = 0.f;
    for (int n = grp; n < NPG; n += 8) acc += base[n*32 + f] * ssig[n];
    sm[grp*32 + f] = acc;
    __syncthreads();
    if (threadIdx.x < 32){
        float s = 0.f;
        for (int g=0; g<8; g++) s += sm[g*32 + threadIdx.x];
        gp[b*32 + threadIdx.x] = s;
    }
}

// ---------------- NTN + head -----------------------------------------------
__global__ void __launch_bounds__(512) k_ntn(const float* __restrict__ ntnW,
                                             const float* __restrict__ ntnV,
                                             const float* __restrict__ ntnb,
                                             const float* __restrict__ fc1W,
                                             const float* __restrict__ fc1b,
                                             const float* __restrict__ scW,
                                             const float* __restrict__ scb,
                                             float* __restrict__ out){
    int b = blockIdx.x;
    __shared__ float sp1[32], sp2[32], sred[512], sfeat[32], sh[16];
    int tid = threadIdx.x;
    if (tid < 32){ sp1[tid] = g_p1[b*32+tid]; sp2[tid] = g_p2[b*32+tid]; }
    __syncthreads();
    int j = tid >> 4, k = tid & 15;
    float acc = 0.f;
    #pragma unroll 8
    for (int i=0; i<32; i++) acc += sp1[i] * ntnW[i*512 + j*16 + k];
    sred[tid] = acc * sp2[j];
    __syncthreads();
    for (int off=256; off>=16; off>>=1){
        if (tid < off) sred[tid] += sred[tid+off];
        __syncthreads();
    }
    if (tid < 16){
        float blk = 0.f;
        for (int i=0; i<32; i++)
            blk += sp1[i]*ntnV[tid*64 + i] + sp2[i]*ntnV[tid*64 + 32 + i];
        sfeat[tid] = fmaxf(sred[tid] + blk + ntnb[tid], 0.f);
        float ck  = (tid==0)  ? 262144.0f : g_hist[b*NBINS + tid];
        float ck1 = (tid==15) ? 0.0f      : g_hist[b*NBINS + tid + 1];
        sfeat[16 + tid] = (ck - ck1) * (1.0f/262144.0f);
    }
    __syncthreads();
    if (tid < 16){
        float h = fc1b[tid];
        for (int m=0; m<32; m++) h += sfeat[m]*fc1W[m*16 + tid];
        sh[tid] = fmaxf(h, 0.f);
    }
    __syncthreads();
    if (tid == 0){
        float o = scb[0];
        for (int n=0; n<16; n++) o += sh[n]*scW[n];
        out[b] = 1.0f/(1.0f + expf(-o));
    }
}

// ---------------- launch ----------------------------------------------------
static void run_side(const float* x, const int* ei, int E,
                     const float* W1, const float* b1,
                     const float* W2, const float* b2,
                     const float* W3, const float* b3, int side){
    const int* src = ei;
    const int* dst = ei + E;
    k_deg_count<<<(E+255)/256, 256>>>(dst, E);
    k_deg_fin<<<TOT/256, 256>>>();

    k_gemm<128,64><<<TOT/32, 256>>>(x, W1, 0);
    k_scatter<64><<<(E*16)/256, 256>>>(src, dst, E);
    k_fin<64,true><<<TOT*64/4/256, 256>>>(b1, 0);

    k_gemm<64,64><<<TOT/32, 256>>>(nullptr, W2, 1);
    k_scatter<64><<<(E*16)/256, 256>>>(src, dst, E);
    k_fin<64,true><<<TOT*64/4/256, 256>>>(b2, 0);

    k_gemm<64,32><<<TOT/32, 256>>>(nullptr, W3, 1);
    k_scatter<32><<<(E*8)/256, 256>>>(src, dst, E);
    k_fin<32,false><<<TOT*32/4/256, 256>>>(b3, side);
}

extern "C" void kernel_launch(void* const* d_in, const int* in_sizes, int n_in,
                              void* d_out, int out_size) {
    const float* x1   = (const float*)d_in[0];
    const float* x2   = (const float*)d_in[1];
    const int*   ei1  = (const int*)d_in[2];
    const int*   ei2  = (const int*)d_in[3];
    const float* W1   = (const float*)d_in[6];
    const float* b1   = (const float*)d_in[7];
    const float* W2   = (const float*)d_in[8];
    const float* b2   = (const float*)d_in[9];
    const float* W3   = (const float*)d_in[10];
    const float* b3   = (const float*)d_in[11];
    const float* attW = (const float*)d_in[12];
    const float* ntnW = (const float*)d_in[13];
    const float* ntnV = (const float*)d_in[14];
    const float* ntnb = (const float*)d_in[15];
    const float* fc1W = (const float*)d_in[16];
    const float* fc1b = (const float*)d_in[17];
    const float* scW  = (const float*)d_in[18];
    const float* scb  = (const float*)d_in[19];
    float* out = (float*)d_out;
    int E = in_sizes[2] / 2;

    run_side(x1, ei1, E, W1, b1, W2, b2, W3, b3, 1);
    run_side(x2, ei2, E, W1, b1, W2, b2, W3, b3, 2);

    k_hist_init<<<8, 256>>>();
    k_dot<<<BGR*16, 256>>>();
    k_thr<<<1, 128>>>();
    k_bin<<<dim3(4, BGR), 256>>>();

    k_att1<<<BGR, 256>>>(attW, 1);
    k_att2<<<BGR, 256>>>(1);
    k_att1<<<BGR, 256>>>(attW, 2);
    k_att2<<<BGR, 256>>>(2);

    k_ntn<<<BGR, 512>>>(ntnW, ntnV, ntnb, fc1W, fc1b, scW, scb, out);
}

// round 4
// speedup vs baseline: 1.0020x; 1.0020x over previous
#include <cuda_runtime.h>
#include <math.h>

#define TOT 65536
#define BGR 128
#define NPG 512
#define NBINS 16

// ---------------- scratch (__device__ globals; zero-init at load) ----------
__device__ float g_deg[TOT];            // zero-maintained
__device__ float g_dis[TOT];
__device__ float g_invdeg[TOT];
__device__ float g_h0[TOT*64];
__device__ float g_agg[TOT*64];         // zero-maintained
__device__ float g_h1[TOT*64];
__device__ float g_af1[TOT*32];
__device__ float g_af2[TOT*32];
__device__ float g_tdot[(size_t)BGR*NPG*NPG];   // 134MB raw dot scratch
__device__ unsigned g_minu[BGR];
__device__ unsigned g_maxu[BGR];
__device__ float g_thr[BGR*15];
__device__ float g_hist[BGR*NBINS];     // slots 1..15 = cumulative counts
__device__ float g_ctx[BGR*32];
__device__ float g_p1[BGR*32];
__device__ float g_p2[BGR*32];

// ---------------- helpers ---------------------------------------------------
__device__ __forceinline__ unsigned f2o(float f){
    unsigned u = __float_as_uint(f);
    return (u & 0x80000000u) ? ~u : (u | 0x80000000u);
}
__device__ __forceinline__ float o2f(unsigned u){
    return __uint_as_float((u & 0x80000000u) ? (u & 0x7fffffffu) : ~u);
}
__device__ __forceinline__ void red_add4(float* p, float4 v){
    asm volatile("red.global.add.v4.f32 [%0], {%1,%2,%3,%4};"
                 :: "l"(p), "f"(v.x), "f"(v.y), "f"(v.z), "f"(v.w) : "memory");
}

// ---------------- degree ----------------------------------------------------
__global__ void k_deg_count(const int* __restrict__ dst, int E){
    int i = blockIdx.x*256 + threadIdx.x;
    if (i < E) atomicAdd(&g_deg[dst[i]], 1.0f);
}
__global__ void k_deg_fin(){
    int i = blockIdx.x*256 + threadIdx.x;
    float d = g_deg[i] + 1.0f;
    g_dis[i]    = rsqrtf(d);
    g_invdeg[i] = 1.0f/d;
    g_deg[i]    = 0.0f;          // restore zero invariant
}

// ---------------- dense GEMM: g_h0 = X @ W  (X: TOT x K, W: K x M) ----------
template<int K, int M>
__global__ void __launch_bounds__(256) k_gemm(const float* __restrict__ Xext,
                                              const float* __restrict__ W,
                                              int use_h1){
    constexpr int R   = 32;
    constexpr int CPT = M/16;
    __shared__ float sX[R*K];
    __shared__ float sW[K*M];
    const float* X = use_h1 ? g_h1 : Xext;
    int row0 = blockIdx.x * R;

    for (int i = threadIdx.x; i < K*M/4; i += 256)
        ((float4*)sW)[i] = ((const float4*)W)[i];
    const float4* Xg = (const float4*)(X + (size_t)row0*K);
    for (int i = threadIdx.x; i < R*K/4; i += 256)
        ((float4*)sX)[i] = Xg[i];
    __syncthreads();

    int tx = threadIdx.x & 15, ty = threadIdx.x >> 4;
    int c0 = tx*CPT, r0 = ty*2;
    float acc0[CPT] = {}, acc1[CPT] = {};

    #pragma unroll
    for (int k = 0; k < K; k += 4){
        float4 xa = *(const float4*)&sX[ r0   *K + k];
        float4 xb = *(const float4*)&sX[(r0+1)*K + k];
        #pragma unroll
        for (int kk = 0; kk < 4; kk++){
            float va = (&xa.x)[kk];
            float vb = (&xb.x)[kk];
            if (CPT == 4){
                float4 wv = *(const float4*)&sW[(k+kk)*M + c0];
                acc0[0] += va*wv.x; acc0[1] += va*wv.y; acc0[2] += va*wv.z; acc0[3] += va*wv.w;
                acc1[0] += vb*wv.x; acc1[1] += vb*wv.y; acc1[2] += vb*wv.z; acc1[3] += vb*wv.w;
            } else {
                float2 wv = *(const float2*)&sW[(k+kk)*M + c0];
                acc0[0] += va*wv.x; acc0[1] += va*wv.y;
                acc1[0] += vb*wv.x; acc1[1] += vb*wv.y;
            }
        }
    }
    float* O0 = &g_h0[(size_t)(row0 + r0    )*M + c0];
    float* O1 = &g_h0[(size_t)(row0 + r0 + 1)*M + c0];
    if (CPT == 4){
        *(float4*)O0 = make_float4(acc0[0],acc0[1],acc0[2],acc0[3]);
        *(float4*)O1 = make_float4(acc1[0],acc1[1],acc1[2],acc1[3]);
    } else {
        *(float2*)O0 = make_float2(acc0[0],acc0[1]);
        *(float2*)O1 = make_float2(acc1[0],acc1[1]);
    }
}

// ---------------- edge scatter: agg[dst] += h0[src]*dis[src] ----------------
template<int F>
__global__ void __launch_bounds__(256) k_scatter(const int* __restrict__ src,
                                                 const int* __restrict__ dst, int E){
    constexpr int G  = F/4;
    constexpr int SH = (F==64) ? 4 : 3;
    int t = blockIdx.x*256 + threadIdx.x;
    int e = t >> SH, j = t & (G-1);
    if (e >= E) return;
    int s = __ldg(src + e), d = __ldg(dst + e);
    float sc = __ldg(&g_dis[s]);
    float4 v = *(const float4*)&g_h0[(size_t)s*F + 4*j];
    red_add4(&g_agg[(size_t)d*F + 4*j],
             make_float4(v.x*sc, v.y*sc, v.z*sc, v.w*sc));
}

// ---------------- finalize: out = [relu](agg*dis + h0*invdeg + b); agg=0 ----
template<int F, bool RELU>
__global__ void __launch_bounds__(256) k_fin(const float* __restrict__ bias, int out_sel){
    constexpr int SH = (F==64) ? 4 : 3;
    int v = blockIdx.x*256 + threadIdx.x;      // float4 index
    int row = v >> SH;
    int f4  = v & ((F/4)-1);
    float4 a = ((float4*)g_agg)[v];
    float4 h = ((const float4*)g_h0)[v];
    float di = g_dis[row], iv = g_invdeg[row];
    float4 bb = ((const float4*)bias)[f4];
    float4 o;
    o.x = a.x*di + h.x*iv + bb.x;
    o.y = a.y*di + h.y*iv + bb.y;
    o.z = a.z*di + h.z*iv + bb.z;
    o.w = a.w*di + h.w*iv + bb.w;
    if (RELU){
        o.x = fmaxf(o.x,0.f); o.y = fmaxf(o.y,0.f);
        o.z = fmaxf(o.z,0.f); o.w = fmaxf(o.w,0.f);
    }
    float* out = (out_sel==0) ? g_h1 : (out_sel==1 ? g_af1 : g_af2);
    ((float4*)out)[v] = o;
    ((float4*)g_agg)[v] = make_float4(0.f,0.f,0.f,0.f);
}

// ---------------- histogram -------------------------------------------------
__global__ void k_hist_init(){
    int t = blockIdx.x*256 + threadIdx.x;
    if (t < BGR){ g_minu[t] = 0xFFFFFFFFu; g_maxu[t] = 0u; }
    if (t < BGR*NBINS) g_hist[t] = 0.f;
}

__global__ void __launch_bounds__(256) k_dot(){
    __shared__ float sA[32*129];
    __shared__ float sB[32*129];
    int b    = blockIdx.x >> 4;
    int tile = blockIdx.x & 15;
    int i0 = (tile >> 2) * 128, j0 = (tile & 3) * 128;
    const float* A  = g_af1 + ((size_t)b*NPG + i0)*32;
    const float* Bp = g_af2 + ((size_t)b*NPG + j0)*32;
    for (int idx = threadIdx.x; idx < 128*32; idx += 256){
        int r = idx >> 5, k = idx & 31;
        sA[k*129 + r] = A[idx];
        sB[k*129 + r] = Bp[idx];
    }
    __syncthreads();
    int tx = threadIdx.x & 15, ty = threadIdx.x >> 4;
    float acc[8][8] = {};
    #pragma unroll
    for (int k = 0; k < 32; k++){
        float av[8], bv[8];
        #pragma unroll
        for (int a=0;a<8;a++) av[a] = sA[k*129 + ty + 16*a];
        #pragma unroll
        for (int c=0;c<8;c++) bv[c] = sB[k*129 + tx + 16*c];
        #pragma unroll
        for (int a=0;a<8;a++)
            #pragma unroll
            for (int c=0;c<8;c++) acc[a][c] += av[a]*bv[c];
    }
    float lmin = acc[0][0], lmax = acc[0][0];
    float* od = g_tdot + ((size_t)b << 18);
    #pragma unroll
    for (int a=0;a<8;a++){
        int i = i0 + ty + 16*a;
        #pragma unroll
        for (int c=0;c<8;c++){
            float v = acc[a][c];
            lmin = fminf(lmin, v); lmax = fmaxf(lmax, v);
            od[(size_t)i*NPG + j0 + tx + 16*c] = v;
        }
    }
    #pragma unroll
    for (int off=16; off; off>>=1){
        lmin = fminf(lmin, __shfl_down_sync(0xffffffffu, lmin, off));
        lmax = fmaxf(lmax, __shfl_down_sync(0xffffffffu, lmax, off));
    }
    __shared__ float wmn[8], wmx[8];
    int w = threadIdx.x >> 5;
    if ((threadIdx.x & 31) == 0){ wmn[w] = lmin; wmx[w] = lmax; }
    __syncthreads();
    if (threadIdx.x == 0){
        float m = wmn[0], M = wmx[0];
        for (int q=1;q<8;q++){ m = fminf(m, wmn[q]); M = fmaxf(M, wmx[q]); }
        atomicMin(&g_minu[b], f2o(m));
        atomicMax(&g_maxu[b], f2o(M));
    }
}

__global__ void k_thr(){
    int b = threadIdx.x;
    if (b >= BGR) return;
    float tmin = o2f(g_minu[b]), tmax = o2f(g_maxu[b]);
    float mn = 1.0f/(1.0f + expf(-tmin));
    float mx = 1.0f/(1.0f + expf(-tmax));
    float rng = (mx > mn) ? (mx - mn) : 1.0f;
    const float PINF = __int_as_float(0x7f800000);
    for (int k = 1; k <= 15; k++){
        float p = mn + rng * (k * (1.0f/16.0f));
        float thr;
        if (p <= 0.0f)      thr = -PINF;
        else if (p >= 1.0f) thr =  PINF;
        else                thr = logf(p / (1.0f - p));
        g_thr[b*15 + k - 1] = thr;
    }
}

__global__ void __launch_bounds__(256) k_bin(){
    int b = blockIdx.y;
    int chunk = blockIdx.x;   // 0..3
    const float4* base = (const float4*)(g_tdot + ((size_t)b << 18))
                         + ((size_t)chunk << 14) + threadIdx.x;
    float thr[15];
    #pragma unroll
    for (int k=0;k<15;k++) thr[k] = g_thr[b*15 + k];
    float c[15] = {};
    for (int it = 0; it < 64; it++){
        float4 v = base[it*256];
        #pragma unroll
        for (int k=0;k<15;k++){
            c[k] += (v.x >= thr[k]) ? 1.0f : 0.0f;
            c[k] += (v.y >= thr[k]) ? 1.0f : 0.0f;
            c[k] += (v.z >= thr[k]) ? 1.0f : 0.0f;
            c[k] += (v.w >= thr[k]) ? 1.0f : 0.0f;
        }
    }
    #pragma unroll
    for (int off=16; off; off>>=1)
        #pragma unroll
        for (int k=0;k<15;k++)
            c[k] += __shfl_down_sync(0xffffffffu, c[k], off);
    if ((threadIdx.x & 31) == 0)
        #pragma unroll
        for (int k=0;k<15;k++)
            atomicAdd(&g_hist[b*NBINS + k + 1], c[k]);
}

// ---------------- attention pooling ----------------------------------------
__global__ void __launch_bounds__(256) k_att1(const float* __restrict__ attW, int sel){
    const float* af = (sel==1) ? g_af1 : g_af2;
    int b = blockIdx.x;
    __shared__ float sm[8*32], smean[32];
    int f = threadIdx.x & 31, grp = threadIdx.x >> 5;
    const float* base = af + (size_t)b*NPG*32;
    float acc = 0.f;
    for (int n = grp; n < NPG; n += 8) acc += base[n*32 + f];
    sm[grp*32 + f] = acc;
    __syncthreads();
    if (threadIdx.x < 32){
        float m = 0.f;
        for (int g=0; g<8; g++) m += sm[g*32 + threadIdx.x];
        smean[threadIdx.x] = m * (1.0f/512.0f);
    }
    __syncthreads();
    if (threadIdx.x < 32){
        int j = threadIdx.x;
        float t = 0.f;
        for (int ff=0; ff<32; ff++) t += smean[ff]*attW[ff*32 + j];
        g_ctx[b*32 + j] = tanhf(t);
    }
}

__global__ void __launch_bounds__(256) k_att2(int sel){
    const float* af = (sel==1) ? g_af1 : g_af2;
    float* gp       = (sel==1) ? g_p1  : g_p2;
    int b = blockIdx.x;
    __shared__ float st[32];
    __shared__ float ssig[NPG];
    __shared__ float sm[8*32];
    if (threadIdx.x < 32) st[threadIdx.x] = g_ctx[b*32 + threadIdx.x];
    __syncthreads();
    const float* base = af + (size_t)b*NPG*32;
    for (int n = threadIdx.x; n < NPG; n += 256){
        float d = 0.f;
        #pragma unroll
        for (int q=0; q<8; q++){
            float4 v = *(const float4*)(base + n*32 + q*4);
            d += v.x*st[q*4] + v.y*st[q*4+1] + v.z*st[q*4+2] + v.w*st[q*4+3];
        }
        ssig[n] = 1.0f/(1.0f + __expf(-d));
    }
    __syncthreads();
    int f = threadIdx.x & 31, grp = threadIdx.x >> 5;
    float acc = 0.f;
    for (int n = grp; n < NPG; n += 8) acc += base[n*32 + f] * ssig[n];
    sm[grp*32 + f] = acc;
    __syncthreads();
    if (threadIdx.x < 32){
        float s = 0.f;
        for (int g=0; g<8; g++) s += sm[g*32 + threadIdx.x];
        gp[b*32 + threadIdx.x] = s;
    }
}

// ---------------- NTN + head -----------------------------------------------
__global__ void __launch_bounds__(512) k_ntn(const float* __restrict__ ntnW,
                                             const float* __restrict__ ntnV,
                                             const float* __restrict__ ntnb,
                                             const float* __restrict__ fc1W,
                                             const float* __restrict__ fc1b,
                                             const float* __restrict__ scW,
                                             const float* __restrict__ scb,
                                             float* __restrict__ out){
    int b = blockIdx.x;
    __shared__ float sp1[32], sp2[32], sred[512], sfeat[32], sh[16];
    int tid = threadIdx.x;
    if (tid < 32){ sp1[tid] = g_p1[b*32+tid]; sp2[tid] = g_p2[b*32+tid]; }
    __syncthreads();
    int j = tid >> 4, k = tid & 15;
    float acc = 0.f;
    #pragma unroll 8
    for (int i=0; i<32; i++) acc += sp1[i] * ntnW[i*512 + j*16 + k];
    sred[tid] = acc * sp2[j];
    __syncthreads();
    for (int off=256; off>=16; off>>=1){
        if (tid < off) sred[tid] += sred[tid+off];
        __syncthreads();
    }
    if (tid < 16){
        float blk = 0.f;
        for (int i=0; i<32; i++)
            blk += sp1[i]*ntnV[tid*64 + i] + sp2[i]*ntnV[tid*64 + 32 + i];
        sfeat[tid] = fmaxf(sred[tid] + blk + ntnb[tid], 0.f);
        float ck  = (tid==0)  ? 262144.0f : g_hist[b*NBINS + tid];
        float ck1 = (tid==15) ? 0.0f      : g_hist[b*NBINS + tid + 1];
        sfeat[16 + tid] = (ck - ck1) * (1.0f/262144.0f);
    }
    __syncthreads();
    if (tid < 16){
        float h = fc1b[tid];
        for (int m=0; m<32; m++) h += sfeat[m]*fc1W[m*16 + tid];
        sh[tid] = fmaxf(h, 0.f);
    }
    __syncthreads();
    if (tid == 0){
        float o = scb[0];
        for (int n=0; n<16; n++) o += sh[n]*scW[n];
        out[b] = 1.0f/(1.0f + expf(-o));
    }
}

// ---------------- launch ----------------------------------------------------
static void run_side(const float* x, const int* ei, int E,
                     const float* W1, const float* b1,
                     const float* W2, const float* b2,
                     const float* W3, const float* b3, int side){
    const int* src = ei;
    const int* dst = ei + E;
    k_deg_count<<<(E+255)/256, 256>>>(dst, E);
    k_deg_fin<<<TOT/256, 256>>>();

    k_gemm<128,64><<<TOT/32, 256>>>(x, W1, 0);
    k_scatter<64><<<(E*16)/256, 256>>>(src, dst, E);
    k_fin<64,true><<<TOT*64/4/256, 256>>>(b1, 0);

    k_gemm<64,64><<<TOT/32, 256>>>(nullptr, W2, 1);
    k_scatter<64><<<(E*16)/256, 256>>>(src, dst, E);
    k_fin<64,true><<<TOT*64/4/256, 256>>>(b2, 0);

    k_gemm<64,32><<<TOT/32, 256>>>(nullptr, W3, 1);
    k_scatter<32><<<(E*8)/256, 256>>>(src, dst, E);
    k_fin<32,false><<<TOT*32/4/256, 256>>>(b3, side);
}

extern "C" void kernel_launch(void* const* d_in, const int* in_sizes, int n_in,
                              void* d_out, int out_size) {
    const float* x1   = (const float*)d_in[0];
    const float* x2   = (const float*)d_in[1];
    const int*   ei1  = (const int*)d_in[2];
    const int*   ei2  = (const int*)d_in[3];
    const float* W1   = (const float*)d_in[6];
    const float* b1   = (const float*)d_in[7];
    const float* W2   = (const float*)d_in[8];
    const float* b2   = (const float*)d_in[9];
    const float* W3   = (const float*)d_in[10];
    const float* b3   = (const float*)d_in[11];
    const float* attW = (const float*)d_in[12];
    const float* ntnW = (const float*)d_in[13];
    const float* ntnV = (const float*)d_in[14];
    const float* ntnb = (const float*)d_in[15];
    const float* fc1W = (const float*)d_in[16];
    const float* fc1b = (const float*)d_in[17];
    const float* scW  = (const float*)d_in[18];
    const float* scb  = (const float*)d_in[19];
    float* out = (float*)d_out;
    int E = in_sizes[2] / 2;

    run_side(x1, ei1, E, W1, b1, W2, b2, W3, b3, 1);
    run_side(x2, ei2, E, W1, b1, W2, b2, W3, b3, 2);

    k_hist_init<<<8, 256>>>();
    k_dot<<<BGR*16, 256>>>();
    k_thr<<<1, 128>>>();
    k_bin<<<dim3(4, BGR), 256>>>();

    k_att1<<<BGR, 256>>>(attW, 1);
    k_att2<<<BGR, 256>>>(1);
    k_att1<<<BGR, 256>>>(attW, 2);
    k_att2<<<BGR, 256>>>(2);

    k_ntn<<<BGR, 512>>>(ntnW, ntnV, ntnb, fc1W, fc1b, scW, scb, out);
}

// round 6
// speedup vs baseline: 1.3487x; 1.3460x over previous
#include <cuda_runtime.h>
#include <math.h>

#define TOT 65536
#define BGR 128
#define NPG 512
#define NBINS 16
#define EDG 1048576   // 16*TOT (asserted against in_sizes at launch)

// ---------------- scratch (__device__ globals; zero-init at load) ----------
__device__ int   g_cnt[TOT];            // zero-maintained (restored in k_scan3)
__device__ int   g_start[TOT+1];
__device__ int   g_cursor[TOT];
__device__ int   g_bsum[256];
__device__ int   g_boff[256];
__device__ int   g_srcs[EDG];
__device__ float g_dis[TOT];
__device__ float g_h0[TOT*64];          // GEMM output, pre-scaled by dis[row]
__device__ float g_h1[TOT*64];
__device__ float g_af1[TOT*32];
__device__ float g_af2[TOT*32];
__device__ float g_tdot[(size_t)BGR*NPG*NPG];   // 134MB raw dot scratch
__device__ unsigned g_minu[BGR];
__device__ unsigned g_maxu[BGR];
__device__ float g_thr[BGR*15];
__device__ float g_hist[BGR*NBINS];     // slots 1..15 = cumulative counts
__device__ float g_ctx[BGR*32];
__device__ float g_p1[BGR*32];
__device__ float g_p2[BGR*32];

// ---------------- helpers ---------------------------------------------------
__device__ __forceinline__ unsigned f2o(float f){
    unsigned u = __float_as_uint(f);
    return (u & 0x80000000u) ? ~u : (u | 0x80000000u);
}
__device__ __forceinline__ float o2f(unsigned u){
    return __uint_as_float((u & 0x80000000u) ? (u & 0x7fffffffu) : ~u);
}

// ---------------- CSR build --------------------------------------------------
__global__ void k_count(const int* __restrict__ dst, int E){
    int i = blockIdx.x*256 + threadIdx.x;
    if (i < E) atomicAdd(&g_cnt[dst[i]], 1);
}

__global__ void k_scan1(){
    __shared__ int s[256];
    int i = blockIdx.x*256 + threadIdx.x;
    int c = g_cnt[i];
    s[threadIdx.x] = c;
    __syncthreads();
    #pragma unroll
    for (int off = 1; off < 256; off <<= 1){
        int t = (threadIdx.x >= off) ? s[threadIdx.x - off] : 0;
        __syncthreads();
        s[threadIdx.x] += t;
        __syncthreads();
    }
    g_start[i] = s[threadIdx.x] - c;          // local exclusive scan
    if (threadIdx.x == 255) g_bsum[blockIdx.x] = s[255];
}

__global__ void k_scan2(){
    __shared__ int s[256];
    int c = g_bsum[threadIdx.x];
    s[threadIdx.x] = c;
    __syncthreads();
    #pragma unroll
    for (int off = 1; off < 256; off <<= 1){
        int t = (threadIdx.x >= off) ? s[threadIdx.x - off] : 0;
        __syncthreads();
        s[threadIdx.x] += t;
        __syncthreads();
    }
    g_boff[threadIdx.x] = s[threadIdx.x] - c;  // exclusive block offsets
}

__global__ void k_scan3(int E){
    int i = blockIdx.x*256 + threadIdx.x;
    int st = g_start[i] + g_boff[i >> 8];
    g_start[i]  = st;
    g_cursor[i] = st;
    float d = (float)g_cnt[i] + 1.0f;
    g_dis[i] = rsqrtf(d);
    g_cnt[i] = 0;                              // restore zero invariant
    if (i == 0) g_start[TOT] = E;
}

__global__ void k_fill(const int* __restrict__ src,
                       const int* __restrict__ dst, int E){
    int i = blockIdx.x*256 + threadIdx.x;
    if (i < E){
        int d = dst[i];
        int pos = atomicAdd(&g_cursor[d], 1);
        g_srcs[pos] = src[i];
    }
}

// ---------------- dense GEMM: g_h0 = (X @ W) * dis[row]  --------------------
template<int K, int M>
__global__ void __launch_bounds__(256) k_gemm(const float* __restrict__ Xext,
                                              const float* __restrict__ W,
                                              int use_h1){
    constexpr int R   = 32;
    constexpr int CPT = M/16;
    __shared__ float sX[R*K];
    __shared__ float sW[K*M];
    const float* X = use_h1 ? g_h1 : Xext;
    int row0 = blockIdx.x * R;

    for (int i = threadIdx.x; i < K*M/4; i += 256)
        ((float4*)sW)[i] = ((const float4*)W)[i];
    const float4* Xg = (const float4*)(X + (size_t)row0*K);
    for (int i = threadIdx.x; i < R*K/4; i += 256)
        ((float4*)sX)[i] = Xg[i];
    __syncthreads();

    int tx = threadIdx.x & 15, ty = threadIdx.x >> 4;
    int c0 = tx*CPT, r0 = ty*2;
    float acc0[CPT] = {}, acc1[CPT] = {};

    #pragma unroll
    for (int k = 0; k < K; k += 4){
        float4 xa = *(const float4*)&sX[ r0   *K + k];
        float4 xb = *(const float4*)&sX[(r0+1)*K + k];
        #pragma unroll
        for (int kk = 0; kk < 4; kk++){
            float va = (&xa.x)[kk];
            float vb = (&xb.x)[kk];
            if (CPT == 4){
                float4 wv = *(const float4*)&sW[(k+kk)*M + c0];
                acc0[0] += va*wv.x; acc0[1] += va*wv.y; acc0[2] += va*wv.z; acc0[3] += va*wv.w;
                acc1[0] += vb*wv.x; acc1[1] += vb*wv.y; acc1[2] += vb*wv.z; acc1[3] += vb*wv.w;
            } else {
                float2 wv = *(const float2*)&sW[(k+kk)*M + c0];
                acc0[0] += va*wv.x; acc0[1] += va*wv.y;
                acc1[0] += vb*wv.x; acc1[1] += vb*wv.y;
            }
        }
    }
    float d0 = g_dis[row0 + r0];
    float d1 = g_dis[row0 + r0 + 1];
    float* O0 = &g_h0[(size_t)(row0 + r0    )*M + c0];
    float* O1 = &g_h0[(size_t)(row0 + r0 + 1)*M + c0];
    if (CPT == 4){
        *(float4*)O0 = make_float4(acc0[0]*d0, acc0[1]*d0, acc0[2]*d0, acc0[3]*d0);
        *(float4*)O1 = make_float4(acc1[0]*d1, acc1[1]*d1, acc1[2]*d1, acc1[3]*d1);
    } else {
        *(float2*)O0 = make_float2(acc0[0]*d0, acc0[1]*d0);
        *(float2*)O1 = make_float2(acc1[0]*d1, acc1[1]*d1);
    }
}

// ------ fused gather+finalize: out = relu?((Σ_in h0s[src] + h0s[row])*dis + b)
template<int F, bool RELU>
__global__ void __launch_bounds__(256) k_gf(const float* __restrict__ bias,
                                            int out_sel){
    constexpr int G  = F/4;
    constexpr int SH = (F==64) ? 4 : 3;
    int t   = blockIdx.x*256 + threadIdx.x;
    int row = t >> SH;
    int j   = t & (G-1);

    // self term (h0s already scaled by dis[row])
    float4 acc = *(const float4*)&g_h0[(size_t)row*F + 4*j];

    int e  = g_start[row];
    int e1 = g_start[row+1];
    for (; e + 1 < e1; e += 2){
        int sa = __ldg(&g_srcs[e]);
        int sb = __ldg(&g_srcs[e+1]);
        float4 va = *(const float4*)&g_h0[(size_t)sa*F + 4*j];
        float4 vb = *(const float4*)&g_h0[(size_t)sb*F + 4*j];
        acc.x += va.x + vb.x; acc.y += va.y + vb.y;
        acc.z += va.z + vb.z; acc.w += va.w + vb.w;
    }
    if (e < e1){
        int sa = __ldg(&g_srcs[e]);
        float4 va = *(const float4*)&g_h0[(size_t)sa*F + 4*j];
        acc.x += va.x; acc.y += va.y; acc.z += va.z; acc.w += va.w;
    }

    float di = g_dis[row];
    float4 bb = ((const float4*)bias)[j];
    float4 o;
    o.x = acc.x*di + bb.x;
    o.y = acc.y*di + bb.y;
    o.z = acc.z*di + bb.z;
    o.w = acc.w*di + bb.w;
    if (RELU){
        o.x = fmaxf(o.x,0.f); o.y = fmaxf(o.y,0.f);
        o.z = fmaxf(o.z,0.f); o.w = fmaxf(o.w,0.f);
    }
    float* out = (out_sel==0) ? g_h1 : (out_sel==1 ? g_af1 : g_af2);
    ((float4*)out)[t] = o;
}

// ---------------- histogram -------------------------------------------------
__global__ void k_hist_init(){
    int t = blockIdx.x*256 + threadIdx.x;
    if (t < BGR){ g_minu[t] = 0xFFFFFFFFu; g_maxu[t] = 0u; }
    if (t < BGR*NBINS) g_hist[t] = 0.f;
}

__global__ void __launch_bounds__(256) k_dot(){
    __shared__ float sA[32*129];
    __shared__ float sB[32*129];
    int b    = blockIdx.x >> 4;
    int tile = blockIdx.x & 15;
    int i0 = (tile >> 2) * 128, j0 = (tile & 3) * 128;
    const float* A  = g_af1 + ((size_t)b*NPG + i0)*32;
    const float* Bp = g_af2 + ((size_t)b*NPG + j0)*32;
    for (int idx = threadIdx.x; idx < 128*32; idx += 256){
        int r = idx >> 5, k = idx & 31;
        sA[k*129 + r] = A[idx];
        sB[k*129 + r] = Bp[idx];
    }
    __syncthreads();
    int tx = threadIdx.x & 15, ty = threadIdx.x >> 4;
    float acc[8][8] = {};
    #pragma unroll
    for (int k = 0; k < 32; k++){
        float av[8], bv[8];
        #pragma unroll
        for (int a=0;a<8;a++) av[a] = sA[k*129 + ty + 16*a];
        #pragma unroll
        for (int c=0;c<8;c++) bv[c] = sB[k*129 + tx + 16*c];
        #pragma unroll
        for (int a=0;a<8;a++)
            #pragma unroll
            for (int c=0;c<8;c++) acc[a][c] += av[a]*bv[c];
    }
    float lmin = acc[0][0], lmax = acc[0][0];
    float* od = g_tdot + ((size_t)b << 18);
    #pragma unroll
    for (int a=0;a<8;a++){
        int i = i0 + ty + 16*a;
        #pragma unroll
        for (int c=0;c<8;c++){
            float v = acc[a][c];
            lmin = fminf(lmin, v); lmax = fmaxf(lmax, v);
            od[(size_t)i*NPG + j0 + tx + 16*c] = v;
        }
    }
    #pragma unroll
    for (int off=16; off; off>>=1){
        lmin = fminf(lmin, __shfl_down_sync(0xffffffffu, lmin, off));
        lmax = fmaxf(lmax, __shfl_down_sync(0xffffffffu, lmax, off));
    }
    __shared__ float wmn[8], wmx[8];
    int w = threadIdx.x >> 5;
    if ((threadIdx.x & 31) == 0){ wmn[w] = lmin; wmx[w] = lmax; }
    __syncthreads();
    if (threadIdx.x == 0){
        float m = wmn[0], M = wmx[0];
        for (int q=1;q<8;q++){ m = fminf(m, wmn[q]); M = fmaxf(M, wmx[q]); }
        atomicMin(&g_minu[b], f2o(m));
        atomicMax(&g_maxu[b], f2o(M));
    }
}

__global__ void k_thr(){
    int b = threadIdx.x;
    if (b >= BGR) return;
    float tmin = o2f(g_minu[b]), tmax = o2f(g_maxu[b]);
    float mn = 1.0f/(1.0f + expf(-tmin));
    float mx = 1.0f/(1.0f + expf(-tmax));
    float rng = (mx > mn) ? (mx - mn) : 1.0f;
    const float PINF = __int_as_float(0x7f800000);
    for (int k = 1; k <= 15; k++){
        float p = mn + rng * (k * (1.0f/16.0f));
        float thr;
        if (p <= 0.0f)      thr = -PINF;
        else if (p >= 1.0f) thr =  PINF;
        else                thr = logf(p / (1.0f - p));
        g_thr[b*15 + k - 1] = thr;
    }
}

__global__ void __launch_bounds__(256) k_bin(){
    int b = blockIdx.y;
    int chunk = blockIdx.x;   // 0..3
    const float4* base = (const float4*)(g_tdot + ((size_t)b << 18))
                         + ((size_t)chunk << 14) + threadIdx.x;
    float thr[15];
    #pragma unroll
    for (int k=0;k<15;k++) thr[k] = g_thr[b*15 + k];
    float c[15] = {};
    for (int it = 0; it < 64; it++){
        float4 v = base[it*256];
        #pragma unroll
        for (int k=0;k<15;k++){
            c[k] += (v.x >= thr[k]) ? 1.0f : 0.0f;
            c[k] += (v.y >= thr[k]) ? 1.0f : 0.0f;
            c[k] += (v.z >= thr[k]) ? 1.0f : 0.0f;
            c[k] += (v.w >= thr[k]) ? 1.0f : 0.0f;
        }
    }
    #pragma unroll
    for (int off=16; off; off>>=1)
        #pragma unroll
        for (int k=0;k<15;k++)
            c[k] += __shfl_down_sync(0xffffffffu, c[k], off);
    if ((threadIdx.x & 31) == 0)
        #pragma unroll
        for (int k=0;k<15;k++)
            atomicAdd(&g_hist[b*NBINS + k + 1], c[k]);
}

// ---------------- attention pooling ----------------------------------------
__global__ void __launch_bounds__(256) k_att1(const float* __restrict__ attW, int sel){
    const float* af = (sel==1) ? g_af1 : g_af2;
    int b = blockIdx.x;
    __shared__ float sm[8*32], smean[32];
    int f = threadIdx.x & 31, grp = threadIdx.x >> 5;
    const float* base = af + (size_t)b*NPG*32;
    float acc = 0.f;
    for (int n = grp; n < NPG; n += 8) acc += base[n*32 + f];
    sm[grp*32 + f] = acc;
    __syncthreads();
    if (threadIdx.x < 32){
        float m = 0.f;
        for (int g=0; g<8; g++) m += sm[g*32 + threadIdx.x];
        smean[threadIdx.x] = m * (1.0f/512.0f);
    }
    __syncthreads();
    if (threadIdx.x < 32){
        int j = threadIdx.x;
        float t = 0.f;
        for (int ff=0; ff<32; ff++) t += smean[ff]*attW[ff*32 + j];
        g_ctx[b*32 + j] = tanhf(t);
    }
}

__global__ void __launch_bounds__(256) k_att2(int sel){
    const float* af = (sel==1) ? g_af1 : g_af2;
    float* gp       = (sel==1) ? g_p1  : g_p2;
    int b = blockIdx.x;
    __shared__ float st[32];
    __shared__ float ssig[NPG];
    __shared__ float sm[8*32];
    if (threadIdx.x < 32) st[threadIdx.x] = g_ctx[b*32 + threadIdx.x];
    __syncthreads();
    const float* base = af + (size_t)b*NPG*32;
    for (int n = threadIdx.x; n < NPG; n += 256){
        float d = 0.f;
        #pragma unroll
        for (int q=0; q<8; q++){
            float4 v = *(const float4*)(base + n*32 + q*4);
            d += v.x*st[q*4] + v.y*st[q*4+1] + v.z*st[q*4+2] + v.w*st[q*4+3];
        }
        ssig[n] = 1.0f/(1.0f + __expf(-d));
    }
    __syncthreads();
    int f = threadIdx.x & 31, grp = threadIdx.x >> 5;
    float acc = 0.f;
    for (int n = grp; n < NPG; n += 8) acc += base[n*32 + f] * ssig[n];
    sm[grp*32 + f] = acc;
    __syncthreads();
    if (threadIdx.x < 32){
        float s = 0.f;
        for (int g=0; g<8; g++) s += sm[g*32 + threadIdx.x];
        gp[b*32 + threadIdx.x] = s;
    }
}

// ---------------- NTN + head -----------------------------------------------
__global__ void __launch_bounds__(512) k_ntn(const float* __restrict__ ntnW,
                                             const float* __restrict__ ntnV,
                                             const float* __restrict__ ntnb,
                                             const float* __restrict__ fc1W,
                                             const float* __restrict__ fc1b,
                                             const float* __restrict__ scW,
                                             const float* __restrict__ scb,
                                             float* __restrict__ out){
    int b = blockIdx.x;
    __shared__ float sp1[32], sp2[32], sred[512], sfeat[32], sh[16];
    int tid = threadIdx.x;
    if (tid < 32){ sp1[tid] = g_p1[b*32+tid]; sp2[tid] = g_p2[b*32+tid]; }
    __syncthreads();
    int j = tid >> 4, k = tid & 15;
    float acc = 0.f;
    #pragma unroll 8
    for (int i=0; i<32; i++) acc += sp1[i] * ntnW[i*512 + j*16 + k];
    sred[tid] = acc * sp2[j];
    __syncthreads();
    for (int off=256; off>=16; off>>=1){
        if (tid < off) sred[tid] += sred[tid+off];
        __syncthreads();
    }
    if (tid < 16){
        float blk = 0.f;
        for (int i=0; i<32; i++)
            blk += sp1[i]*ntnV[tid*64 + i] + sp2[i]*ntnV[tid*64 + 32 + i];
        sfeat[tid] = fmaxf(sred[tid] + blk + ntnb[tid], 0.f);
        float ck  = (tid==0)  ? 262144.0f : g_hist[b*NBINS + tid];
        float ck1 = (tid==15) ? 0.0f      : g_hist[b*NBINS + tid + 1];
        sfeat[16 + tid] = (ck - ck1) * (1.0f/262144.0f);
    }
    __syncthreads();
    if (tid < 16){
        float h = fc1b[tid];
        for (int m=0; m<32; m++) h += sfeat[m]*fc1W[m*16 + tid];
        sh[tid] = fmaxf(h, 0.f);
    }
    __syncthreads();
    if (tid == 0){
        float o = scb[0];
        for (int n=0; n<16; n++) o += sh[n]*scW[n];
        out[b] = 1.0f/(1.0f + expf(-o));
    }
}

// ---------------- launch ----------------------------------------------------
static void run_side(const float* x, const int* ei, int E,
                     const float* W1, const float* b1,
                     const float* W2, const float* b2,
                     const float* W3, const float* b3, int side){
    const int* src = ei;
    const int* dst = ei + E;
    k_count<<<(E+255)/256, 256>>>(dst, E);
    k_scan1<<<256, 256>>>();
    k_scan2<<<1, 256>>>();
    k_scan3<<<TOT/256, 256>>>(E);
    k_fill<<<(E+255)/256, 256>>>(src, dst, E);

    k_gemm<128,64><<<TOT/32, 256>>>(x, W1, 0);
    k_gf<64,true><<<TOT*16/256, 256>>>(b1, 0);

    k_gemm<64,64><<<TOT/32, 256>>>(nullptr, W2, 1);
    k_gf<64,true><<<TOT*16/256, 256>>>(b2, 0);

    k_gemm<64,32><<<TOT/32, 256>>>(nullptr, W3, 1);
    k_gf<32,false><<<TOT*8/256, 256>>>(b3, side);
}

extern "C" void kernel_launch(void* const* d_in, const int* in_sizes, int n_in,
                              void* d_out, int out_size) {
    const float* x1   = (const float*)d_in[0];
    const float* x2   = (const float*)d_in[1];
    const int*   ei1  = (const int*)d_in[2];
    const int*   ei2  = (const int*)d_in[3];
    const float* W1   = (const float*)d_in[6];
    const float* b1   = (const float*)d_in[7];
    const float* W2   = (const float*)d_in[8];
    const float* b2   = (const float*)d_in[9];
    const float* W3   = (const float*)d_in[10];
    const float* b3   = (const float*)d_in[11];
    const float* attW = (const float*)d_in[12];
    const float* ntnW = (const float*)d_in[13];
    const float* ntnV = (const float*)d_in[14];
    const float* ntnb = (const float*)d_in[15];
    const float* fc1W = (const float*)d_in[16];
    const float* fc1b = (const float*)d_in[17];
    const float* scW  = (const float*)d_in[18];
    const float* scb  = (const float*)d_in[19];
    float* out = (float*)d_out;
    int E = in_sizes[2] / 2;

    run_side(x1, ei1, E, W1, b1, W2, b2, W3, b3, 1);
    run_side(x2, ei2, E, W1, b1, W2, b2, W3, b3, 2);

    k_hist_init<<<8, 256>>>();
    k_dot<<<BGR*16, 256>>>();
    k_thr<<<1, 128>>>();
    k_bin<<<dim3(4, BGR), 256>>>();

    k_att1<<<BGR, 256>>>(attW, 1);
    k_att2<<<BGR, 256>>>(1);
    k_att1<<<BGR, 256>>>(attW, 2);
    k_att2<<<BGR, 256>>>(2);

    k_ntn<<<BGR, 512>>>(ntnW, ntnV, ntnb, fc1W, fc1b, scW, scb, out);
}

// round 7
// speedup vs baseline: 1.6631x; 1.2331x over previous
#include <cuda_runtime.h>
#include <math.h>
#include <mma.h>

#define TOT 65536
#define BGR 128
#define NPG 512
#define NBINS 16
#define EDG 1048576   // 16*TOT

// ---------------- scratch (__device__ globals; zero-init at load) ----------
__device__ int   g_cnt[TOT];            // zero-maintained (restored in k_scan3)
__device__ int   g_start[TOT+1];
__device__ int   g_cursor[TOT];
__device__ int   g_bsum[256];
__device__ int   g_boff[256];
__device__ int   g_srcs[EDG];
__device__ float g_dis[TOT];
__device__ float g_h0[TOT*64];          // GEMM output, pre-scaled by dis[row]
__device__ float g_h1[TOT*64];
__device__ float g_af1[TOT*32];
__device__ float g_af2[TOT*32];
__device__ float g_tdot[(size_t)BGR*NPG*NPG];   // 134MB raw dot scratch
__device__ unsigned g_minu[BGR];
__device__ unsigned g_maxu[BGR];
__device__ float g_thr[BGR*15];
__device__ float g_hist[BGR*NBINS];     // slots 1..15 = cumulative counts
__device__ float g_ctx[BGR*32];
__device__ float g_p1[BGR*32];
__device__ float g_p2[BGR*32];

// ---------------- helpers ---------------------------------------------------
__device__ __forceinline__ unsigned f2o(float f){
    unsigned u = __float_as_uint(f);
    return (u & 0x80000000u) ? ~u : (u | 0x80000000u);
}
__device__ __forceinline__ float o2f(unsigned u){
    return __uint_as_float((u & 0x80000000u) ? (u & 0x7fffffffu) : ~u);
}

// ---------------- CSR build --------------------------------------------------
__global__ void k_count(const int* __restrict__ dst, int E){
    int i = blockIdx.x*256 + threadIdx.x;
    if (i < E) atomicAdd(&g_cnt[dst[i]], 1);
}

__global__ void k_scan1(){
    __shared__ int s[256];
    int i = blockIdx.x*256 + threadIdx.x;
    int c = g_cnt[i];
    s[threadIdx.x] = c;
    __syncthreads();
    #pragma unroll
    for (int off = 1; off < 256; off <<= 1){
        int t = (threadIdx.x >= off) ? s[threadIdx.x - off] : 0;
        __syncthreads();
        s[threadIdx.x] += t;
        __syncthreads();
    }
    g_start[i] = s[threadIdx.x] - c;          // local exclusive scan
    if (threadIdx.x == 255) g_bsum[blockIdx.x] = s[255];
}

__global__ void k_scan2(){
    __shared__ int s[256];
    int c = g_bsum[threadIdx.x];
    s[threadIdx.x] = c;
    __syncthreads();
    #pragma unroll
    for (int off = 1; off < 256; off <<= 1){
        int t = (threadIdx.x >= off) ? s[threadIdx.x - off] : 0;
        __syncthreads();
        s[threadIdx.x] += t;
        __syncthreads();
    }
    g_boff[threadIdx.x] = s[threadIdx.x] - c;  // exclusive block offsets
}

__global__ void k_scan3(int E){
    int i = blockIdx.x*256 + threadIdx.x;
    int st = g_start[i] + g_boff[i >> 8];
    g_start[i]  = st;
    g_cursor[i] = st;
    float d = (float)g_cnt[i] + 1.0f;
    g_dis[i] = rsqrtf(d);
    g_cnt[i] = 0;                              // restore zero invariant
    if (i == 0) g_start[TOT] = E;
}

__global__ void k_fill(const int* __restrict__ src,
                       const int* __restrict__ dst, int E){
    int i = blockIdx.x*256 + threadIdx.x;
    if (i < E){
        int d = dst[i];
        int pos = atomicAdd(&g_cursor[d], 1);
        g_srcs[pos] = src[i];
    }
}

// ------ dense GEMM via tf32 wmma: g_h0 = (X @ W) * dis[row] -----------------
// R = 2048/M rows per block; K chunked at 64; smem padded (+4) for ldsm.
template<int K, int M>
__global__ void __launch_bounds__(256) k_gemm(const float* __restrict__ Xext,
                                              const float* __restrict__ W,
                                              int use_h1){
    using namespace nvcuda;
    constexpr int R  = 2048 / M;     // 32 (M=64) or 64 (M=32)
    constexpr int CT = M / 16;       // col tiles
    constexpr int KP = 68;           // 64 + 4 pad
    constexpr int MP = M + 4;
    __shared__ float sX[R * KP];
    __shared__ float sW[64 * MP];

    const float* X = use_h1 ? g_h1 : Xext;
    int row0 = blockIdx.x * R;
    int warp = threadIdx.x >> 5;
    int tr = warp / CT, tc = warp % CT;

    wmma::fragment<wmma::accumulator, 16, 16, 8, float> c;
    wmma::fill_fragment(c, 0.0f);

    for (int kc = 0; kc < K; kc += 64){
        for (int i = threadIdx.x; i < R * 16; i += 256){
            int r = i >> 4, c4 = i & 15;
            ((float4*)(sX + r * KP))[c4] =
                ((const float4*)(X + (size_t)(row0 + r) * K + kc))[c4];
        }
        for (int i = threadIdx.x; i < 64 * (M / 4); i += 256){
            int r = i / (M / 4), c4 = i % (M / 4);
            ((float4*)(sW + r * MP))[c4] =
                ((const float4*)(W + (size_t)(kc + r) * M))[c4];
        }
        __syncthreads();
        #pragma unroll
        for (int k0 = 0; k0 < 64; k0 += 8){
            wmma::fragment<wmma::matrix_a, 16, 16, 8, wmma::precision::tf32, wmma::row_major> a;
            wmma::fragment<wmma::matrix_b, 16, 16, 8, wmma::precision::tf32, wmma::row_major> bf;
            wmma::load_matrix_sync(a,  sX + tr * 16 * KP + k0, KP);
            wmma::load_matrix_sync(bf, sW + k0 * MP + tc * 16, MP);
            #pragma unroll
            for (int q = 0; q < a.num_elements;  q++) a.x[q]  = wmma::__float_to_tf32(a.x[q]);
            #pragma unroll
            for (int q = 0; q < bf.num_elements; q++) bf.x[q] = wmma::__float_to_tf32(bf.x[q]);
            wmma::mma_sync(c, a, bf, c);
        }
        __syncthreads();
    }

    // epilogue: stash tiles in sX, then scaled vectorized writes
    float* sO = sX;                  // R*M floats = 8KB, fits
    wmma::store_matrix_sync(sO + tr * 16 * M + tc * 16, c, M, wmma::mem_row_major);
    __syncthreads();
    constexpr int MV = M / 4;
    for (int i = threadIdx.x; i < R * MV; i += 256){
        int r = i / MV;
        float d = g_dis[row0 + r];
        float4 v = ((float4*)sO)[i];
        ((float4*)(g_h0 + (size_t)row0 * M))[i] =
            make_float4(v.x * d, v.y * d, v.z * d, v.w * d);
    }
}

// ------ fused gather+finalize: out = relu?((Σ_in h0s[src] + h0s[row])*dis + b)
template<int F, bool RELU>
__global__ void __launch_bounds__(256) k_gf(const float* __restrict__ bias,
                                            int out_sel){
    constexpr int G  = F/4;
    constexpr int SH = (F==64) ? 4 : 3;
    int t   = blockIdx.x*256 + threadIdx.x;
    int row = t >> SH;
    int j   = t & (G-1);

    float4 acc = *(const float4*)&g_h0[(size_t)row*F + 4*j];  // self term

    int e  = g_start[row];
    int e1 = g_start[row+1];
    for (; e + 1 < e1; e += 2){
        int sa = __ldg(&g_srcs[e]);
        int sb = __ldg(&g_srcs[e+1]);
        float4 va = *(const float4*)&g_h0[(size_t)sa*F + 4*j];
        float4 vb = *(const float4*)&g_h0[(size_t)sb*F + 4*j];
        acc.x += va.x + vb.x; acc.y += va.y + vb.y;
        acc.z += va.z + vb.z; acc.w += va.w + vb.w;
    }
    if (e < e1){
        int sa = __ldg(&g_srcs[e]);
        float4 va = *(const float4*)&g_h0[(size_t)sa*F + 4*j];
        acc.x += va.x; acc.y += va.y; acc.z += va.z; acc.w += va.w;
    }

    float di = g_dis[row];
    float4 bb = ((const float4*)bias)[j];
    float4 o;
    o.x = acc.x*di + bb.x;
    o.y = acc.y*di + bb.y;
    o.z = acc.z*di + bb.z;
    o.w = acc.w*di + bb.w;
    if (RELU){
        o.x = fmaxf(o.x,0.f); o.y = fmaxf(o.y,0.f);
        o.z = fmaxf(o.z,0.f); o.w = fmaxf(o.w,0.f);
    }
    float* out = (out_sel==0) ? g_h1 : (out_sel==1 ? g_af1 : g_af2);
    ((float4*)out)[t] = o;
}

// ---------------- histogram -------------------------------------------------
__global__ void k_hist_init(){
    int t = blockIdx.x*256 + threadIdx.x;
    if (t < BGR){ g_minu[t] = 0xFFFFFFFFu; g_maxu[t] = 0u; }
    if (t < BGR*NBINS) g_hist[t] = 0.f;
}

// dot via tf32 wmma: 128x128 tile per block, K=32; min/max + store to g_tdot
__global__ void __launch_bounds__(256) k_dot(){
    using namespace nvcuda;
    constexpr int LD = 36;           // 32 + 4 pad
    __shared__ float sA[128*LD];
    __shared__ float sB[128*LD];
    int b    = blockIdx.x >> 4;
    int tile = blockIdx.x & 15;
    int i0 = (tile >> 2) * 128, j0 = (tile & 3) * 128;
    const float* A  = g_af1 + ((size_t)b*NPG + i0)*32;
    const float* Bp = g_af2 + ((size_t)b*NPG + j0)*32;
    for (int i = threadIdx.x; i < 128*8; i += 256){
        int r = i >> 3, c4 = i & 7;
        ((float4*)(sA + r*LD))[c4] = ((const float4*)(A  + (size_t)r*32))[c4];
        ((float4*)(sB + r*LD))[c4] = ((const float4*)(Bp + (size_t)r*32))[c4];
    }
    __syncthreads();

    int warp = threadIdx.x >> 5;     // warp -> 16-row strip
    float* od = g_tdot + ((size_t)b << 18);
    float lmin = INFINITY, lmax = -INFINITY;

    #pragma unroll
    for (int tc = 0; tc < 8; tc++){
        wmma::fragment<wmma::accumulator, 16, 16, 8, float> c;
        wmma::fill_fragment(c, 0.0f);
        #pragma unroll
        for (int k0 = 0; k0 < 32; k0 += 8){
            wmma::fragment<wmma::matrix_a, 16, 16, 8, wmma::precision::tf32, wmma::row_major> a;
            wmma::fragment<wmma::matrix_b, 16, 16, 8, wmma::precision::tf32, wmma::col_major> bf;
            wmma::load_matrix_sync(a,  sA + warp*16*LD + k0, LD);
            wmma::load_matrix_sync(bf, sB + tc*16*LD  + k0, LD);
            #pragma unroll
            for (int q = 0; q < a.num_elements;  q++) a.x[q]  = wmma::__float_to_tf32(a.x[q]);
            #pragma unroll
            for (int q = 0; q < bf.num_elements; q++) bf.x[q] = wmma::__float_to_tf32(bf.x[q]);
            wmma::mma_sync(c, a, bf, c);
        }
        #pragma unroll
        for (int q = 0; q < c.num_elements; q++){
            lmin = fminf(lmin, c.x[q]); lmax = fmaxf(lmax, c.x[q]);
        }
        wmma::store_matrix_sync(od + (size_t)(i0 + warp*16)*NPG + j0 + tc*16,
                                c, NPG, wmma::mem_row_major);
    }

    #pragma unroll
    for (int off=16; off; off>>=1){
        lmin = fminf(lmin, __shfl_down_sync(0xffffffffu, lmin, off));
        lmax = fmaxf(lmax, __shfl_down_sync(0xffffffffu, lmax, off));
    }
    __shared__ float wmn[8], wmx[8];
    if ((threadIdx.x & 31) == 0){ wmn[warp] = lmin; wmx[warp] = lmax; }
    __syncthreads();
    if (threadIdx.x == 0){
        float m = wmn[0], M = wmx[0];
        for (int q=1;q<8;q++){ m = fminf(m, wmn[q]); M = fmaxf(M, wmx[q]); }
        atomicMin(&g_minu[b], f2o(m));
        atomicMax(&g_maxu[b], f2o(M));
    }
}

__global__ void k_thr(){
    int b = threadIdx.x;
    if (b >= BGR) return;
    float tmin = o2f(g_minu[b]), tmax = o2f(g_maxu[b]);
    float mn = 1.0f/(1.0f + expf(-tmin));
    float mx = 1.0f/(1.0f + expf(-tmax));
    float rng = (mx > mn) ? (mx - mn) : 1.0f;
    const float PINF = __int_as_float(0x7f800000);
    for (int k = 1; k <= 15; k++){
        float p = mn + rng * (k * (1.0f/16.0f));
        float thr;
        if (p <= 0.0f)      thr = -PINF;
        else if (p >= 1.0f) thr =  PINF;
        else                thr = logf(p / (1.0f - p));
        g_thr[b*15 + k - 1] = thr;
    }
}

__global__ void __launch_bounds__(256) k_bin(){
    int b = blockIdx.y;
    int chunk = blockIdx.x;   // 0..3
    const float4* base = (const float4*)(g_tdot + ((size_t)b << 18))
                         + ((size_t)chunk << 14) + threadIdx.x;
    float thr[15];
    #pragma unroll
    for (int k=0;k<15;k++) thr[k] = g_thr[b*15 + k];
    float c[15] = {};
    for (int it = 0; it < 64; it++){
        float4 v = base[it*256];
        #pragma unroll
        for (int k=0;k<15;k++){
            c[k] += (v.x >= thr[k]) ? 1.0f : 0.0f;
            c[k] += (v.y >= thr[k]) ? 1.0f : 0.0f;
            c[k] += (v.z >= thr[k]) ? 1.0f : 0.0f;
            c[k] += (v.w >= thr[k]) ? 1.0f : 0.0f;
        }
    }
    #pragma unroll
    for (int off=16; off; off>>=1)
        #pragma unroll
        for (int k=0;k<15;k++)
            c[k] += __shfl_down_sync(0xffffffffu, c[k], off);
    if ((threadIdx.x & 31) == 0)
        #pragma unroll
        for (int k=0;k<15;k++)
            atomicAdd(&g_hist[b*NBINS + k + 1], c[k]);
}

// ---------------- attention pooling ----------------------------------------
__global__ void __launch_bounds__(256) k_att1(const float* __restrict__ attW, int sel){
    const float* af = (sel==1) ? g_af1 : g_af2;
    int b = blockIdx.x;
    __shared__ float sm[8*32], smean[32];
    int f = threadIdx.x & 31, grp = threadIdx.x >> 5;
    const float* base = af + (size_t)b*NPG*32;
    float acc = 0.f;
    for (int n = grp; n < NPG; n += 8) acc += base[n*32 + f];
    sm[grp*32 + f] = acc;
    __syncthreads();
    if (threadIdx.x < 32){
        float m = 0.f;
        for (int g=0; g<8; g++) m += sm[g*32 + threadIdx.x];
        smean[threadIdx.x] = m * (1.0f/512.0f);
    }
    __syncthreads();
    if (threadIdx.x < 32){
        int j = threadIdx.x;
        float t = 0.f;
        for (int ff=0; ff<32; ff++) t += smean[ff]*attW[ff*32 + j];
        g_ctx[b*32 + j] = tanhf(t);
    }
}

__global__ void __launch_bounds__(256) k_att2(int sel){
    const float* af = (sel==1) ? g_af1 : g_af2;
    float* gp       = (sel==1) ? g_p1  : g_p2;
    int b = blockIdx.x;
    __shared__ float st[32];
    __shared__ float ssig[NPG];
    __shared__ float sm[8*32];
    if (threadIdx.x < 32) st[threadIdx.x] = g_ctx[b*32 + threadIdx.x];
    __syncthreads();
    const float* base = af + (size_t)b*NPG*32;
    for (int n = threadIdx.x; n < NPG; n += 256){
        float d = 0.f;
        #pragma unroll
        for (int q=0; q<8; q++){
            float4 v = *(const float4*)(base + n*32 + q*4);
            d += v.x*st[q*4] + v.y*st[q*4+1] + v.z*st[q*4+2] + v.w*st[q*4+3];
        }
        ssig[n] = 1.0f/(1.0f + __expf(-d));
    }
    __syncthreads();
    int f = threadIdx.x & 31, grp = threadIdx.x >> 5;
    float acc = 0.f;
    for (int n = grp; n < NPG; n += 8) acc += base[n*32 + f] * ssig[n];
    sm[grp*32 + f] = acc;
    __syncthreads();
    if (threadIdx.x < 32){
        float s = 0.f;
        for (int g=0; g<8; g++) s += sm[g*32 + threadIdx.x];
        gp[b*32 + threadIdx.x] = s;
    }
}

// ---------------- NTN + head -----------------------------------------------
__global__ void __launch_bounds__(512) k_ntn(const float* __restrict__ ntnW,
                                             const float* __restrict__ ntnV,
                                             const float* __restrict__ ntnb,
                                             const float* __restrict__ fc1W,
                                             const float* __restrict__ fc1b,
                                             const float* __restrict__ scW,
                                             const float* __restrict__ scb,
                                             float* __restrict__ out){
    int b = blockIdx.x;
    __shared__ float sp1[32], sp2[32], sred[512], sfeat[32], sh[16];
    int tid = threadIdx.x;
    if (tid < 32){ sp1[tid] = g_p1[b*32+tid]; sp2[tid] = g_p2[b*32+tid]; }
    __syncthreads();
    int j = tid >> 4, k = tid & 15;
    float acc = 0.f;
    #pragma unroll 8
    for (int i=0; i<32; i++) acc += sp1[i] * ntnW[i*512 + j*16 + k];
    sred[tid] = acc * sp2[j];
    __syncthreads();
    for (int off=256; off>=16; off>>=1){
        if (tid < off) sred[tid] += sred[tid+off];
        __syncthreads();
    }
    if (tid < 16){
        float blk = 0.f;
        for (int i=0; i<32; i++)
            blk += sp1[i]*ntnV[tid*64 + i] + sp2[i]*ntnV[tid*64 + 32 + i];
        sfeat[tid] = fmaxf(sred[tid] + blk + ntnb[tid], 0.f);
        float ck  = (tid==0)  ? 262144.0f : g_hist[b*NBINS + tid];
        float ck1 = (tid==15) ? 0.0f      : g_hist[b*NBINS + tid + 1];
        sfeat[16 + tid] = (ck - ck1) * (1.0f/262144.0f);
    }
    __syncthreads();
    if (tid < 16){
        float h = fc1b[tid];
        for (int m=0; m<32; m++) h += sfeat[m]*fc1W[m*16 + tid];
        sh[tid] = fmaxf(h, 0.f);
    }
    __syncthreads();
    if (tid == 0){
        float o = scb[0];
        for (int n=0; n<16; n++) o += sh[n]*scW[n];
        out[b] = 1.0f/(1.0f + expf(-o));
    }
}

// ---------------- launch ----------------------------------------------------
static void run_side(const float* x, const int* ei, int E,
                     const float* W1, const float* b1,
                     const float* W2, const float* b2,
                     const float* W3, const float* b3, int side){
    const int* src = ei;
    const int* dst = ei + E;
    k_count<<<(E+255)/256, 256>>>(dst, E);
    k_scan1<<<256, 256>>>();
    k_scan2<<<1, 256>>>();
    k_scan3<<<TOT/256, 256>>>(E);
    k_fill<<<(E+255)/256, 256>>>(src, dst, E);

    k_gemm<128,64><<<TOT/32, 256>>>(x, W1, 0);
    k_gf<64,true><<<TOT*16/256, 256>>>(b1, 0);

    k_gemm<64,64><<<TOT/32, 256>>>(nullptr, W2, 1);
    k_gf<64,true><<<TOT*16/256, 256>>>(b2, 0);

    k_gemm<64,32><<<TOT/64, 256>>>(nullptr, W3, 1);
    k_gf<32,false><<<TOT*8/256, 256>>>(b3, side);
}

extern "C" void kernel_launch(void* const* d_in, const int* in_sizes, int n_in,
                              void* d_out, int out_size) {
    const float* x1   = (const float*)d_in[0];
    const float* x2   = (const float*)d_in[1];
    const int*   ei1  = (const int*)d_in[2];
    const int*   ei2  = (const int*)d_in[3];
    const float* W1   = (const float*)d_in[6];
    const float* b1   = (const float*)d_in[7];
    const float* W2   = (const float*)d_in[8];
    const float* b2   = (const float*)d_in[9];
    const float* W3   = (const float*)d_in[10];
    const float* b3   = (const float*)d_in[11];
    const float* attW = (const float*)d_in[12];
    const float* ntnW = (const float*)d_in[13];
    const float* ntnV = (const float*)d_in[14];
    const float* ntnb = (const float*)d_in[15];
    const float* fc1W = (const float*)d_in[16];
    const float* fc1b = (const float*)d_in[17];
    const float* scW  = (const float*)d_in[18];
    const float* scb  = (const float*)d_in[19];
    float* out = (float*)d_out;
    int E = in_sizes[2] / 2;

    run_side(x1, ei1, E, W1, b1, W2, b2, W3, b3, 1);
    run_side(x2, ei2, E, W1, b1, W2, b2, W3, b3, 2);

    k_hist_init<<<8, 256>>>();
    k_dot<<<BGR*16, 256>>>();
    k_thr<<<1, 128>>>();
    k_bin<<<dim3(4, BGR), 256>>>();

    k_att1<<<BGR, 256>>>(attW, 1);
    k_att2<<<BGR, 256>>>(1);
    k_att1<<<BGR, 256>>>(attW, 2);
    k_att2<<<BGR, 256>>>(2);

    k_ntn<<<BGR, 512>>>(ntnW, ntnV, ntnb, fc1W, fc1b, scW, scb, out);
}

// round 10
// speedup vs baseline: 1.7935x; 1.0784x over previous
#include <cuda_runtime.h>
#include <math.h>
#include <mma.h>

#define TOT 65536
#define BGR 128
#define NPG 512
#define NBINS 16
#define EDG 1048576   // 16*TOT

// ---------------- scratch (__device__ globals; zero-init at load) ----------
// side 1
__device__ int   g_cnt1[TOT];           // zero-maintained
__device__ int   g_start1[TOT+1];
__device__ int   g_cursor1[TOT];
__device__ int   g_bsum1[256];
__device__ int   g_boff1[256];
__device__ int   g_srcs1[EDG];
__device__ float g_dis1[TOT];
__device__ float g_h0a[TOT*64];
__device__ float g_h1a[TOT*64];
// side 2
__device__ int   g_cnt2[TOT];           // zero-maintained
__device__ int   g_start2[TOT+1];
__device__ int   g_cursor2[TOT];
__device__ int   g_bsum2[256];
__device__ int   g_boff2[256];
__device__ int   g_srcs2[EDG];
__device__ float g_dis2[TOT];
__device__ float g_h0b[TOT*64];
__device__ float g_h1b[TOT*64];
// shared tail
__device__ float g_af1[TOT*32];
__device__ float g_af2[TOT*32];
__device__ unsigned g_minu[BGR];
__device__ unsigned g_maxu[BGR];
__device__ float g_thr[BGR*15];
__device__ float g_hist[BGR*NBINS];     // slots 1..15 = cumulative counts
__device__ float g_ctx1[BGR*32];
__device__ float g_ctx2[BGR*32];
__device__ float g_p1[BGR*32];
__device__ float g_p2[BGR*32];

// ---------------- helpers ---------------------------------------------------
__device__ __forceinline__ unsigned f2o(float f){
    unsigned u = __float_as_uint(f);
    return (u & 0x80000000u) ? ~u : (u | 0x80000000u);
}
__device__ __forceinline__ float o2f(unsigned u){
    return __uint_as_float((u & 0x80000000u) ? (u & 0x7fffffffu) : ~u);
}

// ---------------- CSR build (both sides fused via blockIdx.y) ---------------
__global__ void k_count(const int* __restrict__ ei1, const int* __restrict__ ei2,
                        int E){
    int side = blockIdx.y;
    const int* dst = (side ? ei2 : ei1) + E;
    int* cnt = side ? g_cnt2 : g_cnt1;
    int i = blockIdx.x*256 + threadIdx.x;
    if (i < E) atomicAdd(&cnt[dst[i]], 1);
}

__global__ void k_scan1(){
    int side = blockIdx.y;
    const int* cnt = side ? g_cnt2 : g_cnt1;
    int* start = side ? g_start2 : g_start1;
    int* bsum  = side ? g_bsum2  : g_bsum1;
    __shared__ int s[256];
    int i = blockIdx.x*256 + threadIdx.x;
    int c = cnt[i];
    s[threadIdx.x] = c;
    __syncthreads();
    #pragma unroll
    for (int off = 1; off < 256; off <<= 1){
        int t = (threadIdx.x >= off) ? s[threadIdx.x - off] : 0;
        __syncthreads();
        s[threadIdx.x] += t;
        __syncthreads();
    }
    start[i] = s[threadIdx.x] - c;
    if (threadIdx.x == 255) bsum[blockIdx.x] = s[255];
}

__global__ void k_scan2(){
    int side = blockIdx.x;
    const int* bsum = side ? g_bsum2 : g_bsum1;
    int* boff       = side ? g_boff2 : g_boff1;
    __shared__ int s[256];
    int c = bsum[threadIdx.x];
    s[threadIdx.x] = c;
    __syncthreads();
    #pragma unroll
    for (int off = 1; off < 256; off <<= 1){
        int t = (threadIdx.x >= off) ? s[threadIdx.x - off] : 0;
        __syncthreads();
        s[threadIdx.x] += t;
        __syncthreads();
    }
    boff[threadIdx.x] = s[threadIdx.x] - c;
}

__global__ void k_scan3(int E){
    int side = blockIdx.y;
    int* cnt    = side ? g_cnt2    : g_cnt1;
    int* start  = side ? g_start2  : g_start1;
    int* cursor = side ? g_cursor2 : g_cursor1;
    const int* boff = side ? g_boff2 : g_boff1;
    float* dis  = side ? g_dis2    : g_dis1;
    int i = blockIdx.x*256 + threadIdx.x;
    int st = start[i] + boff[i >> 8];
    start[i]  = st;
    cursor[i] = st;
    float d = (float)cnt[i] + 1.0f;
    dis[i] = rsqrtf(d);
    cnt[i] = 0;                              // restore zero invariant
    if (i == 0) start[TOT] = E;
}

__global__ void k_fill(const int* __restrict__ ei1, const int* __restrict__ ei2,
                       int E){
    int side = blockIdx.y;
    const int* ei = side ? ei2 : ei1;
    const int* src = ei;
    const int* dst = ei + E;
    int* cursor = side ? g_cursor2 : g_cursor1;
    int* srcs   = side ? g_srcs2   : g_srcs1;
    int i = blockIdx.x*256 + threadIdx.x;
    if (i < E){
        int d = dst[i];
        int pos = atomicAdd(&cursor[d], 1);
        srcs[pos] = src[i];
    }
}

// ------ dense GEMM via tf32 wmma: H0 = (X @ W) * dis[row], both sides -------
// src_sel = 0: X from args (Xa/Xb). src_sel = 1: X = g_h1a/g_h1b (in-kernel).
template<int K, int M>
__global__ void __launch_bounds__(256) k_gemm(const float* __restrict__ Xa,
                                              const float* __restrict__ Xb,
                                              const float* __restrict__ W,
                                              int src_sel){
    using namespace nvcuda;
    constexpr int R  = 2048 / M;
    constexpr int CT = M / 16;
    constexpr int KP = 68;
    constexpr int MP = M + 4;
    __shared__ float sX[R * KP];
    __shared__ float sW[64 * MP];

    int side = blockIdx.y;
    const float* X = src_sel ? (side ? g_h1b : g_h1a)
                             : (side ? Xb    : Xa);
    const float* dis = side ? g_dis2 : g_dis1;
    float* H0        = side ? g_h0b  : g_h0a;

    int row0 = blockIdx.x * R;
    int warp = threadIdx.x >> 5;
    int tr = warp / CT, tc = warp % CT;

    wmma::fragment<wmma::accumulator, 16, 16, 8, float> c;
    wmma::fill_fragment(c, 0.0f);

    for (int kc = 0; kc < K; kc += 64){
        for (int i = threadIdx.x; i < R * 16; i += 256){
            int r = i >> 4, c4 = i & 15;
            ((float4*)(sX + r * KP))[c4] =
                ((const float4*)(X + (size_t)(row0 + r) * K + kc))[c4];
        }
        for (int i = threadIdx.x; i < 64 * (M / 4); i += 256){
            int r = i / (M / 4), c4 = i % (M / 4);
            ((float4*)(sW + r * MP))[c4] =
                ((const float4*)(W + (size_t)(kc + r) * M))[c4];
        }
        __syncthreads();
        #pragma unroll
        for (int k0 = 0; k0 < 64; k0 += 8){
            wmma::fragment<wmma::matrix_a, 16, 16, 8, wmma::precision::tf32, wmma::row_major> a;
            wmma::fragment<wmma::matrix_b, 16, 16, 8, wmma::precision::tf32, wmma::row_major> bf;
            wmma::load_matrix_sync(a,  sX + tr * 16 * KP + k0, KP);
            wmma::load_matrix_sync(bf, sW + k0 * MP + tc * 16, MP);
            #pragma unroll
            for (int q = 0; q < a.num_elements;  q++) a.x[q]  = wmma::__float_to_tf32(a.x[q]);
            #pragma unroll
            for (int q = 0; q < bf.num_elements; q++) bf.x[q] = wmma::__float_to_tf32(bf.x[q]);
            wmma::mma_sync(c, a, bf, c);
        }
        __syncthreads();
    }

    float* sO = sX;
    wmma::store_matrix_sync(sO + tr * 16 * M + tc * 16, c, M, wmma::mem_row_major);
    __syncthreads();
    constexpr int MV = M / 4;
    for (int i = threadIdx.x; i < R * MV; i += 256){
        int r = i / MV;
        float d = dis[row0 + r];
        float4 v = ((float4*)sO)[i];
        ((float4*)(H0 + (size_t)row0 * M))[i] =
            make_float4(v.x * d, v.y * d, v.z * d, v.w * d);
    }
}

// ------ fused gather+finalize, both sides: out = relu?((Σ+self)*dis + b) ----
template<int F, bool RELU, bool LAST>
__global__ void __launch_bounds__(256) k_gf(const float* __restrict__ bias){
    constexpr int G  = F/4;
    constexpr int SH = (F==64) ? 4 : 3;
    int side = blockIdx.y;
    const float* h0   = side ? g_h0b    : g_h0a;
    const int* srcs   = side ? g_srcs2  : g_srcs1;
    const int* start  = side ? g_start2 : g_start1;
    const float* dis  = side ? g_dis2   : g_dis1;
    float* out = LAST ? (side ? g_af2 : g_af1) : (side ? g_h1b : g_h1a);

    int t   = blockIdx.x*256 + threadIdx.x;
    int row = t >> SH;
    int j   = t & (G-1);

    float4 acc = *(const float4*)&h0[(size_t)row*F + 4*j];   // self term

    int e  = start[row];
    int e1 = start[row+1];
    for (; e + 1 < e1; e += 2){
        int sa = __ldg(&srcs[e]);
        int sb = __ldg(&srcs[e+1]);
        float4 va = *(const float4*)&h0[(size_t)sa*F + 4*j];
        float4 vb = *(const float4*)&h0[(size_t)sb*F + 4*j];
        acc.x += va.x + vb.x; acc.y += va.y + vb.y;
        acc.z += va.z + vb.z; acc.w += va.w + vb.w;
    }
    if (e < e1){
        int sa = __ldg(&srcs[e]);
        float4 va = *(const float4*)&h0[(size_t)sa*F + 4*j];
        acc.x += va.x; acc.y += va.y; acc.z += va.z; acc.w += va.w;
    }

    float di = dis[row];
    float4 bb = ((const float4*)bias)[j];
    float4 o;
    o.x = acc.x*di + bb.x;
    o.y = acc.y*di + bb.y;
    o.z = acc.z*di + bb.z;
    o.w = acc.w*di + bb.w;
    if (RELU){
        o.x = fmaxf(o.x,0.f); o.y = fmaxf(o.y,0.f);
        o.z = fmaxf(o.z,0.f); o.w = fmaxf(o.w,0.f);
    }
    ((float4*)out)[t] = o;
}

// ---------------- histogram -------------------------------------------------
__global__ void k_hist_init(){
    int t = blockIdx.x*256 + threadIdx.x;
    if (t < BGR){ g_minu[t] = 0xFFFFFFFFu; g_maxu[t] = 0u; }
    if (t < BGR*NBINS) g_hist[t] = 0.f;
}

// pass A: tf32 dot min/max only (no stores)
__global__ void __launch_bounds__(256) k_dotA(){
    using namespace nvcuda;
    constexpr int LD = 36;
    __shared__ float sA[128*LD];
    __shared__ float sB[128*LD];
    int b    = blockIdx.x >> 4;
    int tile = blockIdx.x & 15;
    int i0 = (tile >> 2) * 128, j0 = (tile & 3) * 128;
    const float* A  = g_af1 + ((size_t)b*NPG + i0)*32;
    const float* Bp = g_af2 + ((size_t)b*NPG + j0)*32;
    for (int i = threadIdx.x; i < 128*8; i += 256){
        int r = i >> 3, c4 = i & 7;
        ((float4*)(sA + r*LD))[c4] = ((const float4*)(A  + (size_t)r*32))[c4];
        ((float4*)(sB + r*LD))[c4] = ((const float4*)(Bp + (size_t)r*32))[c4];
    }
    __syncthreads();

    int warp = threadIdx.x >> 5;
    float lmin = INFINITY, lmax = -INFINITY;

    #pragma unroll
    for (int tc = 0; tc < 8; tc++){
        wmma::fragment<wmma::accumulator, 16, 16, 8, float> c;
        wmma::fill_fragment(c, 0.0f);
        #pragma unroll
        for (int k0 = 0; k0 < 32; k0 += 8){
            wmma::fragment<wmma::matrix_a, 16, 16, 8, wmma::precision::tf32, wmma::row_major> a;
            wmma::fragment<wmma::matrix_b, 16, 16, 8, wmma::precision::tf32, wmma::col_major> bf;
            wmma::load_matrix_sync(a,  sA + warp*16*LD + k0, LD);
            wmma::load_matrix_sync(bf, sB + tc*16*LD  + k0, LD);
            #pragma unroll
            for (int q = 0; q < a.num_elements;  q++) a.x[q]  = wmma::__float_to_tf32(a.x[q]);
            #pragma unroll
            for (int q = 0; q < bf.num_elements; q++) bf.x[q] = wmma::__float_to_tf32(bf.x[q]);
            wmma::mma_sync(c, a, bf, c);
        }
        #pragma unroll
        for (int q = 0; q < c.num_elements; q++){
            lmin = fminf(lmin, c.x[q]); lmax = fmaxf(lmax, c.x[q]);
        }
    }

    #pragma unroll
    for (int off=16; off; off>>=1){
        lmin = fminf(lmin, __shfl_down_sync(0xffffffffu, lmin, off));
        lmax = fmaxf(lmax, __shfl_down_sync(0xffffffffu, lmax, off));
    }
    __shared__ float wmn[8], wmx[8];
    if ((threadIdx.x & 31) == 0){ wmn[warp] = lmin; wmx[warp] = lmax; }
    __syncthreads();
    if (threadIdx.x == 0){
        float m = wmn[0], M = wmx[0];
        for (int q=1;q<8;q++){ m = fminf(m, wmn[q]); M = fmaxf(M, wmx[q]); }
        atomicMin(&g_minu[b], f2o(m));
        atomicMax(&g_maxu[b], f2o(M));
    }
}

__global__ void k_thr(){
    int b = threadIdx.x;
    if (b >= BGR) return;
    float tmin = o2f(g_minu[b]), tmax = o2f(g_maxu[b]);
    float mn = 1.0f/(1.0f + expf(-tmin));
    float mx = 1.0f/(1.0f + expf(-tmax));
    float rng = (mx > mn) ? (mx - mn) : 1.0f;
    const float PINF = __int_as_float(0x7f800000);
    for (int k = 1; k <= 15; k++){
        float p = mn + rng * (k * (1.0f/16.0f));
        float thr;
        if (p <= 0.0f)      thr = -PINF;
        else if (p >= 1.0f) thr =  PINF;
        else                thr = logf(p / (1.0f - p));
        g_thr[b*15 + k - 1] = thr;
    }
}

// pass B: recompute identical tf32 dots, bin in-register vs 15 thresholds
__global__ void __launch_bounds__(256) k_dotB(){
    using namespace nvcuda;
    constexpr int LD = 36;
    __shared__ float sA[128*LD];
    __shared__ float sB[128*LD];
    __shared__ float scnt[15];
    int b    = blockIdx.x >> 4;
    int tile = blockIdx.x & 15;
    int i0 = (tile >> 2) * 128, j0 = (tile & 3) * 128;
    const float* A  = g_af1 + ((size_t)b*NPG + i0)*32;
    const float* Bp = g_af2 + ((size_t)b*NPG + j0)*32;
    for (int i = threadIdx.x; i < 128*8; i += 256){
        int r = i >> 3, c4 = i & 7;
        ((float4*)(sA + r*LD))[c4] = ((const float4*)(A  + (size_t)r*32))[c4];
        ((float4*)(sB + r*LD))[c4] = ((const float4*)(Bp + (size_t)r*32))[c4];
    }
    if (threadIdx.x < 15) scnt[threadIdx.x] = 0.f;
    float th[15];
    #pragma unroll
    for (int k=0;k<15;k++) th[k] = g_thr[b*15 + k];
    __syncthreads();

    int warp = threadIdx.x >> 5;
    float cnt[15] = {};

    #pragma unroll
    for (int tc = 0; tc < 8; tc++){
        wmma::fragment<wmma::accumulator, 16, 16, 8, float> c;
        wmma::fill_fragment(c, 0.0f);
        #pragma unroll
        for (int k0 = 0; k0 < 32; k0 += 8){
            wmma::fragment<wmma::matrix_a, 16, 16, 8, wmma::precision::tf32, wmma::row_major> a;
            wmma::fragment<wmma::matrix_b, 16, 16, 8, wmma::precision::tf32, wmma::col_major> bf;
            wmma::load_matrix_sync(a,  sA + warp*16*LD + k0, LD);
            wmma::load_matrix_sync(bf, sB + tc*16*LD  + k0, LD);
            #pragma unroll
            for (int q = 0; q < a.num_elements;  q++) a.x[q]  = wmma::__float_to_tf32(a.x[q]);
            #pragma unroll
            for (int q = 0; q < bf.num_elements; q++) bf.x[q] = wmma::__float_to_tf32(bf.x[q]);
            wmma::mma_sync(c, a, bf, c);
        }
        #pragma unroll
        for (int q = 0; q < c.num_elements; q++){
            float v = c.x[q];
            #pragma unroll
            for (int k=0;k<15;k++)
                cnt[k] += (v >= th[k]) ? 1.0f : 0.0f;
        }
    }

    #pragma unroll
    for (int off=16; off; off>>=1)
        #pragma unroll
        for (int k=0;k<15;k++)
            cnt[k] += __shfl_down_sync(0xffffffffu, cnt[k], off);
    if ((threadIdx.x & 31) == 0)
        #pragma unroll
        for (int k=0;k<15;k++)
            atomicAdd(&scnt[k], cnt[k]);
    __syncthreads();
    if (threadIdx.x < 15)
        atomicAdd(&g_hist[b*NBINS + threadIdx.x + 1], scnt[threadIdx.x]);
}

// ---------------- attention pooling (both sides fused) ----------------------
__global__ void __launch_bounds__(256) k_att1(const float* __restrict__ attW){
    int side = blockIdx.y;
    const float* af = side ? g_af2  : g_af1;
    float* ctx      = side ? g_ctx2 : g_ctx1;
    int b = blockIdx.x;
    __shared__ float sm[8*32], smean[32];
    int f = threadIdx.x & 31, grp = threadIdx.x >> 5;
    const float* base = af + (size_t)b*NPG*32;
    float acc = 0.f;
    for (int n = grp; n < NPG; n += 8) acc += base[n*32 + f];
    sm[grp*32 + f] = acc;
    __syncthreads();
    if (threadIdx.x < 32){
        float m = 0.f;
        for (int g=0; g<8; g++) m += sm[g*32 + threadIdx.x];
        smean[threadIdx.x] = m * (1.0f/512.0f);
    }
    __syncthreads();
    if (threadIdx.x < 32){
        int j = threadIdx.x;
        float t = 0.f;
        for (int ff=0; ff<32; ff++) t += smean[ff]*attW[ff*32 + j];
        ctx[b*32 + j] = tanhf(t);
    }
}

__global__ void __launch_bounds__(256) k_att2(){
    int side = blockIdx.y;
    const float* af  = side ? g_af2  : g_af1;
    const float* ctx = side ? g_ctx2 : g_ctx1;
    float* gp        = side ? g_p2   : g_p1;
    int b = blockIdx.x;
    __shared__ float st[32];
    __shared__ float ssig[NPG];
    __shared__ float sm[8*32];
    if (threadIdx.x < 32) st[threadIdx.x] = ctx[b*32 + threadIdx.x];
    __syncthreads();
    const float* base = af + (size_t)b*NPG*32;
    for (int n = threadIdx.x; n < NPG; n += 256){
        float d = 0.f;
        #pragma unroll
        for (int q=0; q<8; q++){
            float4 v = *(const float4*)(base + n*32 + q*4);
            d += v.x*st[q*4] + v.y*st[q*4+1] + v.z*st[q*4+2] + v.w*st[q*4+3];
        }
        ssig[n] = 1.0f/(1.0f + __expf(-d));
    }
    __syncthreads();
    int f = threadIdx.x & 31, grp = threadIdx.x >> 5;
    float acc = 0.f;
    for (int n = grp; n < NPG; n += 8) acc += base[n*32 + f] * ssig[n];
    sm[grp*32 + f] = acc;
    __syncthreads();
    if (threadIdx.x < 32){
        float s = 0.f;
        for (int g=0; g<8; g++) s += sm[g*32 + threadIdx.x];
        gp[b*32 + threadIdx.x] = s;
    }
}

// ---------------- NTN + head -----------------------------------------------
__global__ void __launch_bounds__(512) k_ntn(const float* __restrict__ ntnW,
                                             const float* __restrict__ ntnV,
                                             const float* __restrict__ ntnb,
                                             const float* __restrict__ fc1W,
                                             const float* __restrict__ fc1b,
                                             const float* __restrict__ scW,
                                             const float* __restrict__ scb,
                                             float* __restrict__ out){
    int b = blockIdx.x;
    __shared__ float sp1[32], sp2[32], sred[512], sfeat[32], sh[16];
    int tid = threadIdx.x;
    if (tid < 32){ sp1[tid] = g_p1[b*32+tid]; sp2[tid] = g_p2[b*32+tid]; }
    __syncthreads();
    int j = tid >> 4, k = tid & 15;
    float acc = 0.f;
    #pragma unroll 8
    for (int i=0; i<32; i++) acc += sp1[i] * ntnW[i*512 + j*16 + k];
    sred[tid] = acc * sp2[j];
    __syncthreads();
    for (int off=256; off>=16; off>>=1){
        if (tid < off) sred[tid] += sred[tid+off];
        __syncthreads();
    }
    if (tid < 16){
        float blk = 0.f;
        for (int i=0; i<32; i++)
            blk += sp1[i]*ntnV[tid*64 + i] + sp2[i]*ntnV[tid*64 + 32 + i];
        sfeat[tid] = fmaxf(sred[tid] + blk + ntnb[tid], 0.f);
        float ck  = (tid==0)  ? 262144.0f : g_hist[b*NBINS + tid];
        float ck1 = (tid==15) ? 0.0f      : g_hist[b*NBINS + tid + 1];
        sfeat[16 + tid] = (ck - ck1) * (1.0f/262144.0f);
    }
    __syncthreads();
    if (tid < 16){
        float h = fc1b[tid];
        for (int m=0; m<32; m++) h += sfeat[m]*fc1W[m*16 + tid];
        sh[tid] = fmaxf(h, 0.f);
    }
    __syncthreads();
    if (tid == 0){
        float o = scb[0];
        for (int n=0; n<16; n++) o += sh[n]*scW[n];
        out[b] = 1.0f/(1.0f + expf(-o));
    }
}

// ---------------- launch ----------------------------------------------------
extern "C" void kernel_launch(void* const* d_in, const int* in_sizes, int n_in,
                              void* d_out, int out_size) {
    const float* x1   = (const float*)d_in[0];
    const float* x2   = (const float*)d_in[1];
    const int*   ei1  = (const int*)d_in[2];
    const int*   ei2  = (const int*)d_in[3];
    const float* W1   = (const float*)d_in[6];
    const float* b1   = (const float*)d_in[7];
    const float* W2   = (const float*)d_in[8];
    const float* b2   = (const float*)d_in[9];
    const float* W3   = (const float*)d_in[10];
    const float* b3   = (const float*)d_in[11];
    const float* attW = (const float*)d_in[12];
    const float* ntnW = (const float*)d_in[13];
    const float* ntnV = (const float*)d_in[14];
    const float* ntnb = (const float*)d_in[15];
    const float* fc1W = (const float*)d_in[16];
    const float* fc1b = (const float*)d_in[17];
    const float* scW  = (const float*)d_in[18];
    const float* scb  = (const float*)d_in[19];
    float* out = (float*)d_out;
    int E = in_sizes[2] / 2;

    k_hist_init<<<8, 256>>>();

    // CSR build, both sides fused
    k_count<<<dim3((E+255)/256, 2), 256>>>(ei1, ei2, E);
    k_scan1<<<dim3(256, 2), 256>>>();
    k_scan2<<<2, 256>>>();
    k_scan3<<<dim3(TOT/256, 2), 256>>>(E);
    k_fill<<<dim3((E+255)/256, 2), 256>>>(ei1, ei2, E);

    // GCN stack, both sides fused
    k_gemm<128,64><<<dim3(TOT/32, 2), 256>>>(x1, x2, W1, 0);
    k_gf<64,true,false><<<dim3(TOT*16/256, 2), 256>>>(b1);

    k_gemm<64,64><<<dim3(TOT/32, 2), 256>>>(nullptr, nullptr, W2, 1);
    k_gf<64,true,false><<<dim3(TOT*16/256, 2), 256>>>(b2);

    k_gemm<64,32><<<dim3(TOT/64, 2), 256>>>(nullptr, nullptr, W3, 1);
    k_gf<32,false,true><<<dim3(TOT*8/256, 2), 256>>>(b3);

    // histogram chain
    k_dotA<<<BGR*16, 256>>>();
    k_thr<<<1, 128>>>();
    k_dotB<<<BGR*16, 256>>>();

    // attention, both sides fused
    k_att1<<<dim3(BGR, 2), 256>>>(attW);
    k_att2<<<dim3(BGR, 2), 256>>>();

    k_ntn<<<BGR, 512>>>(ntnW, ntnV, ntnb, fc1W, fc1b, scW, scb, out);
}

// round 11
// speedup vs baseline: 1.8884x; 1.0529x over previous
#include <cuda_runtime.h>
#include <cuda_fp16.h>
#include <math.h>
#include <mma.h>

#define TOT 65536
#define BGR 128
#define NPG 512
#define NBINS 16
#define EDG 1048576   // 16*TOT

// ---------------- scratch (__device__ globals; zero-init at load) ----------
// side 1
__device__ int    g_cnt1[TOT];          // zero-maintained
__device__ int    g_start1[TOT+1];
__device__ int    g_cursor1[TOT];
__device__ int    g_bsum1[256];
__device__ int    g_boff1[256];
__device__ int    g_srcs1[EDG];
__device__ float  g_dis1[TOT];
__device__ __half g_h0a[TOT*64];
__device__ float  g_h1a[TOT*64];
// side 2
__device__ int    g_cnt2[TOT];          // zero-maintained
__device__ int    g_start2[TOT+1];
__device__ int    g_cursor2[TOT];
__device__ int    g_bsum2[256];
__device__ int    g_boff2[256];
__device__ int    g_srcs2[EDG];
__device__ float  g_dis2[TOT];
__device__ __half g_h0b[TOT*64];
__device__ float  g_h1b[TOT*64];
// shared tail
__device__ float g_af1[TOT*32];
__device__ float g_af2[TOT*32];
__device__ unsigned g_minu[BGR];
__device__ unsigned g_maxu[BGR];
__device__ float g_hist[BGR*NBINS];     // slots 1..15 = cumulative counts
__device__ float g_ctx1[BGR*32];
__device__ float g_ctx2[BGR*32];
__device__ float g_p1[BGR*32];
__device__ float g_p2[BGR*32];

// ---------------- helpers ---------------------------------------------------
__device__ __forceinline__ unsigned f2o(float f){
    unsigned u = __float_as_uint(f);
    return (u & 0x80000000u) ? ~u : (u | 0x80000000u);
}
__device__ __forceinline__ float o2f(unsigned u){
    return __uint_as_float((u & 0x80000000u) ? (u & 0x7fffffffu) : ~u);
}
// accumulate 8 halves (packed in uint4) into acc[0..7]
__device__ __forceinline__ void add8(float* acc, uint4 v){
    __half2 h; float2 f;
    *(unsigned*)&h = v.x; f = __half22float2(h); acc[0]+=f.x; acc[1]+=f.y;
    *(unsigned*)&h = v.y; f = __half22float2(h); acc[2]+=f.x; acc[3]+=f.y;
    *(unsigned*)&h = v.z; f = __half22float2(h); acc[4]+=f.x; acc[5]+=f.y;
    *(unsigned*)&h = v.w; f = __half22float2(h); acc[6]+=f.x; acc[7]+=f.y;
}

// ---------------- CSR build (both sides fused via blockIdx.y) ---------------
// block (0,0) also initializes the histogram min/max/count state.
__global__ void k_count(const int* __restrict__ ei1, const int* __restrict__ ei2,
                        int E){
    int side = blockIdx.y;
    if (blockIdx.x == 0 && side == 0){
        if (threadIdx.x < BGR){ g_minu[threadIdx.x] = 0xFFFFFFFFu; g_maxu[threadIdx.x] = 0u; }
        #pragma unroll
        for (int q = 0; q < (BGR*NBINS)/256; q++)
            g_hist[q*256 + threadIdx.x] = 0.f;
    }
    const int* dst = (side ? ei2 : ei1) + E;
    int* cnt = side ? g_cnt2 : g_cnt1;
    int i = blockIdx.x*256 + threadIdx.x;
    if (i < E) atomicAdd(&cnt[dst[i]], 1);
}

__global__ void k_scan1(){
    int side = blockIdx.y;
    const int* cnt = side ? g_cnt2 : g_cnt1;
    int* start = side ? g_start2 : g_start1;
    int* bsum  = side ? g_bsum2  : g_bsum1;
    __shared__ int s[256];
    int i = blockIdx.x*256 + threadIdx.x;
    int c = cnt[i];
    s[threadIdx.x] = c;
    __syncthreads();
    #pragma unroll
    for (int off = 1; off < 256; off <<= 1){
        int t = (threadIdx.x >= off) ? s[threadIdx.x - off] : 0;
        __syncthreads();
        s[threadIdx.x] += t;
        __syncthreads();
    }
    start[i] = s[threadIdx.x] - c;
    if (threadIdx.x == 255) bsum[blockIdx.x] = s[255];
}

__global__ void k_scan2(){
    int side = blockIdx.x;
    const int* bsum = side ? g_bsum2 : g_bsum1;
    int* boff       = side ? g_boff2 : g_boff1;
    __shared__ int s[256];
    int c = bsum[threadIdx.x];
    s[threadIdx.x] = c;
    __syncthreads();
    #pragma unroll
    for (int off = 1; off < 256; off <<= 1){
        int t = (threadIdx.x >= off) ? s[threadIdx.x - off] : 0;
        __syncthreads();
        s[threadIdx.x] += t;
        __syncthreads();
    }
    boff[threadIdx.x] = s[threadIdx.x] - c;
}

__global__ void k_scan3(int E){
    int side = blockIdx.y;
    int* cnt    = side ? g_cnt2    : g_cnt1;
    int* start  = side ? g_start2  : g_start1;
    int* cursor = side ? g_cursor2 : g_cursor1;
    const int* boff = side ? g_boff2 : g_boff1;
    float* dis  = side ? g_dis2    : g_dis1;
    int i = blockIdx.x*256 + threadIdx.x;
    int st = start[i] + boff[i >> 8];
    start[i]  = st;
    cursor[i] = st;
    float d = (float)cnt[i] + 1.0f;
    dis[i] = rsqrtf(d);
    cnt[i] = 0;                              // restore zero invariant
    if (i == 0) start[TOT] = E;
}

__global__ void k_fill(const int* __restrict__ ei1, const int* __restrict__ ei2,
                       int E){
    int side = blockIdx.y;
    const int* ei = side ? ei2 : ei1;
    const int* src = ei;
    const int* dst = ei + E;
    int* cursor = side ? g_cursor2 : g_cursor1;
    int* srcs   = side ? g_srcs2   : g_srcs1;
    int i = blockIdx.x*256 + threadIdx.x;
    if (i < E){
        int d = dst[i];
        int pos = atomicAdd(&cursor[d], 1);
        srcs[pos] = src[i];
    }
}

// ------ dense GEMM via tf32 wmma: H0 = fp16((X @ W) * dis[row]), both sides -
// src_sel = 0: X from args (Xa/Xb). src_sel = 1: X = g_h1a/g_h1b (in-kernel).
template<int K, int M>
__global__ void __launch_bounds__(256) k_gemm(const float* __restrict__ Xa,
                                              const float* __restrict__ Xb,
                                              const float* __restrict__ W,
                                              int src_sel){
    using namespace nvcuda;
    constexpr int R  = 2048 / M;
    constexpr int CT = M / 16;
    constexpr int KP = 68;
    constexpr int MP = M + 4;
    __shared__ float sX[R * KP];
    __shared__ float sW[64 * MP];

    int side = blockIdx.y;
    const float* X = src_sel ? (side ? g_h1b : g_h1a)
                             : (side ? Xb    : Xa);
    const float* dis = side ? g_dis2 : g_dis1;
    __half* H0       = side ? g_h0b  : g_h0a;

    int row0 = blockIdx.x * R;
    int warp = threadIdx.x >> 5;
    int tr = warp / CT, tc = warp % CT;

    wmma::fragment<wmma::accumulator, 16, 16, 8, float> c;
    wmma::fill_fragment(c, 0.0f);

    for (int kc = 0; kc < K; kc += 64){
        for (int i = threadIdx.x; i < R * 16; i += 256){
            int r = i >> 4, c4 = i & 15;
            ((float4*)(sX + r * KP))[c4] =
                ((const float4*)(X + (size_t)(row0 + r) * K + kc))[c4];
        }
        for (int i = threadIdx.x; i < 64 * (M / 4); i += 256){
            int r = i / (M / 4), c4 = i % (M / 4);
            ((float4*)(sW + r * MP))[c4] =
                ((const float4*)(W + (size_t)(kc + r) * M))[c4];
        }
        __syncthreads();
        #pragma unroll
        for (int k0 = 0; k0 < 64; k0 += 8){
            wmma::fragment<wmma::matrix_a, 16, 16, 8, wmma::precision::tf32, wmma::row_major> a;
            wmma::fragment<wmma::matrix_b, 16, 16, 8, wmma::precision::tf32, wmma::row_major> bf;
            wmma::load_matrix_sync(a,  sX + tr * 16 * KP + k0, KP);
            wmma::load_matrix_sync(bf, sW + k0 * MP + tc * 16, MP);
            #pragma unroll
            for (int q = 0; q < a.num_elements;  q++) a.x[q]  = wmma::__float_to_tf32(a.x[q]);
            #pragma unroll
            for (int q = 0; q < bf.num_elements; q++) bf.x[q] = wmma::__float_to_tf32(bf.x[q]);
            wmma::mma_sync(c, a, bf, c);
        }
        __syncthreads();
    }

    float* sO = sX;
    wmma::store_matrix_sync(sO + tr * 16 * M + tc * 16, c, M, wmma::mem_row_major);
    __syncthreads();
    constexpr int MH = M / 8;           // uint4 (8 halves) per row chunk
    for (int i = threadIdx.x; i < R * MH; i += 256){
        int r = i / MH;
        float d = dis[row0 + r];
        float4 v0 = ((float4*)sO)[i*2];
        float4 v1 = ((float4*)sO)[i*2 + 1];
        __half2 ha = __floats2half2_rn(v0.x*d, v0.y*d);
        __half2 hb = __floats2half2_rn(v0.z*d, v0.w*d);
        __half2 hc = __floats2half2_rn(v1.x*d, v1.y*d);
        __half2 hd = __floats2half2_rn(v1.z*d, v1.w*d);
        uint4 u;
        u.x = *(unsigned*)&ha; u.y = *(unsigned*)&hb;
        u.z = *(unsigned*)&hc; u.w = *(unsigned*)&hd;
        ((uint4*)(H0 + (size_t)row0 * M))[i] = u;
    }
}

// ------ fused gather+finalize, both sides: out = relu?((Σ+self)*dis + b) ----
// h0 is fp16 (8 halves per 16B load); accumulation fp32; G = F/8 thr/node.
template<int F, bool RELU, bool LAST>
__global__ void __launch_bounds__(256) k_gf(const float* __restrict__ bias){
    constexpr int G  = F/8;
    constexpr int SH = (F==64) ? 3 : 2;
    int side = blockIdx.y;
    const __half* h0  = side ? g_h0b    : g_h0a;
    const int* srcs   = side ? g_srcs2  : g_srcs1;
    const int* start  = side ? g_start2 : g_start1;
    const float* dis  = side ? g_dis2   : g_dis1;
    float* out = LAST ? (side ? g_af2 : g_af1) : (side ? g_h1b : g_h1a);

    int t   = blockIdx.x*256 + threadIdx.x;
    int row = t >> SH;
    int j   = t & (G-1);

    float acc[8] = {};
    add8(acc, ((const uint4*)(h0 + (size_t)row*F))[j]);      // self term

    int e  = start[row];
    int e1 = start[row+1];
    for (; e + 1 < e1; e += 2){
        int sa = __ldg(&srcs[e]);
        int sb = __ldg(&srcs[e+1]);
        uint4 va = ((const uint4*)(h0 + (size_t)sa*F))[j];
        uint4 vb = ((const uint4*)(h0 + (size_t)sb*F))[j];
        add8(acc, va);
        add8(acc, vb);
    }
    if (e < e1){
        int sa = __ldg(&srcs[e]);
        add8(acc, ((const uint4*)(h0 + (size_t)sa*F))[j]);
    }

    float di = dis[row];
    float4 b0 = ((const float4*)bias)[2*j];
    float4 b1 = ((const float4*)bias)[2*j + 1];
    float4 o0, o1;
    o0.x = acc[0]*di + b0.x; o0.y = acc[1]*di + b0.y;
    o0.z = acc[2]*di + b0.z; o0.w = acc[3]*di + b0.w;
    o1.x = acc[4]*di + b1.x; o1.y = acc[5]*di + b1.y;
    o1.z = acc[6]*di + b1.z; o1.w = acc[7]*di + b1.w;
    if (RELU){
        o0.x = fmaxf(o0.x,0.f); o0.y = fmaxf(o0.y,0.f);
        o0.z = fmaxf(o0.z,0.f); o0.w = fmaxf(o0.w,0.f);
        o1.x = fmaxf(o1.x,0.f); o1.y = fmaxf(o1.y,0.f);
        o1.z = fmaxf(o1.z,0.f); o1.w = fmaxf(o1.w,0.f);
    }
    ((float4*)out)[2*t]     = o0;
    ((float4*)out)[2*t + 1] = o1;
}

// ---------------- histogram -------------------------------------------------
// pass A: tf32 dot min/max only (no stores)
__global__ void __launch_bounds__(256) k_dotA(){
    using namespace nvcuda;
    constexpr int LD = 36;
    __shared__ float sA[128*LD];
    __shared__ float sB[128*LD];
    int b    = blockIdx.x >> 4;
    int tile = blockIdx.x & 15;
    int i0 = (tile >> 2) * 128, j0 = (tile & 3) * 128;
    const float* A  = g_af1 + ((size_t)b*NPG + i0)*32;
    const float* Bp = g_af2 + ((size_t)b*NPG + j0)*32;
    for (int i = threadIdx.x; i < 128*8; i += 256){
        int r = i >> 3, c4 = i & 7;
        ((float4*)(sA + r*LD))[c4] = ((const float4*)(A  + (size_t)r*32))[c4];
        ((float4*)(sB + r*LD))[c4] = ((const float4*)(Bp + (size_t)r*32))[c4];
    }
    __syncthreads();

    int warp = threadIdx.x >> 5;
    float lmin = INFINITY, lmax = -INFINITY;

    #pragma unroll
    for (int tc = 0; tc < 8; tc++){
        wmma::fragment<wmma::accumulator, 16, 16, 8, float> c;
        wmma::fill_fragment(c, 0.0f);
        #pragma unroll
        for (int k0 = 0; k0 < 32; k0 += 8){
            wmma::fragment<wmma::matrix_a, 16, 16, 8, wmma::precision::tf32, wmma::row_major> a;
            wmma::fragment<wmma::matrix_b, 16, 16, 8, wmma::precision::tf32, wmma::col_major> bf;
            wmma::load_matrix_sync(a,  sA + warp*16*LD + k0, LD);
            wmma::load_matrix_sync(bf, sB + tc*16*LD  + k0, LD);
            #pragma unroll
            for (int q = 0; q < a.num_elements;  q++) a.x[q]  = wmma::__float_to_tf32(a.x[q]);
            #pragma unroll
            for (int q = 0; q < bf.num_elements; q++) bf.x[q] = wmma::__float_to_tf32(bf.x[q]);
            wmma::mma_sync(c, a, bf, c);
        }
        #pragma unroll
        for (int q = 0; q < c.num_elements; q++){
            lmin = fminf(lmin, c.x[q]); lmax = fmaxf(lmax, c.x[q]);
        }
    }

    #pragma unroll
    for (int off=16; off; off>>=1){
        lmin = fminf(lmin, __shfl_down_sync(0xffffffffu, lmin, off));
        lmax = fmaxf(lmax, __shfl_down_sync(0xffffffffu, lmax, off));
    }
    __shared__ float wmn[8], wmx[8];
    if ((threadIdx.x & 31) == 0){ wmn[warp] = lmin; wmx[warp] = lmax; }
    __syncthreads();
    if (threadIdx.x == 0){
        float m = wmn[0], M = wmx[0];
        for (int q=1;q<8;q++){ m = fminf(m, wmn[q]); M = fmaxf(M, wmx[q]); }
        atomicMin(&g_minu[b], f2o(m));
        atomicMax(&g_maxu[b], f2o(M));
    }
}

// pass B: recompute identical tf32 dots, thresholds computed per-block,
// bin in-register vs 15 thresholds
__global__ void __launch_bounds__(256) k_dotB(){
    using namespace nvcuda;
    constexpr int LD = 36;
    __shared__ float sA[128*LD];
    __shared__ float sB[128*LD];
    __shared__ float sth[15];
    __shared__ float scnt[15];
    int b    = blockIdx.x >> 4;
    int tile = blockIdx.x & 15;
    int i0 = (tile >> 2) * 128, j0 = (tile & 3) * 128;
    const float* A  = g_af1 + ((size_t)b*NPG + i0)*32;
    const float* Bp = g_af2 + ((size_t)b*NPG + j0)*32;
    for (int i = threadIdx.x; i < 128*8; i += 256){
        int r = i >> 3, c4 = i & 7;
        ((float4*)(sA + r*LD))[c4] = ((const float4*)(A  + (size_t)r*32))[c4];
        ((float4*)(sB + r*LD))[c4] = ((const float4*)(Bp + (size_t)r*32))[c4];
    }
    if (threadIdx.x < 15){
        scnt[threadIdx.x] = 0.f;
        // thresholds in t-space (pullback of equal-width sigmoid bins)
        float tmin = o2f(g_minu[b]), tmax = o2f(g_maxu[b]);
        float mn = 1.0f/(1.0f + expf(-tmin));
        float mx = 1.0f/(1.0f + expf(-tmax));
        float rng = (mx > mn) ? (mx - mn) : 1.0f;
        const float PINF = __int_as_float(0x7f800000);
        float p = mn + rng * ((threadIdx.x + 1) * (1.0f/16.0f));
        float thr;
        if (p <= 0.0f)      thr = -PINF;
        else if (p >= 1.0f) thr =  PINF;
        else                thr = logf(p / (1.0f - p));
        sth[threadIdx.x] = thr;
    }
    __syncthreads();

    float th[15];
    #pragma unroll
    for (int k=0;k<15;k++) th[k] = sth[k];

    int warp = threadIdx.x >> 5;
    float cnt[15] = {};

    #pragma unroll
    for (int tc = 0; tc < 8; tc++){
        wmma::fragment<wmma::accumulator, 16, 16, 8, float> c;
        wmma::fill_fragment(c, 0.0f);
        #pragma unroll
        for (int k0 = 0; k0 < 32; k0 += 8){
            wmma::fragment<wmma::matrix_a, 16, 16, 8, wmma::precision::tf32, wmma::row_major> a;
            wmma::fragment<wmma::matrix_b, 16, 16, 8, wmma::precision::tf32, wmma::col_major> bf;
            wmma::load_matrix_sync(a,  sA + warp*16*LD + k0, LD);
            wmma::load_matrix_sync(bf, sB + tc*16*LD  + k0, LD);
            #pragma unroll
            for (int q = 0; q < a.num_elements;  q++) a.x[q]  = wmma::__float_to_tf32(a.x[q]);
            #pragma unroll
            for (int q = 0; q < bf.num_elements; q++) bf.x[q] = wmma::__float_to_tf32(bf.x[q]);
            wmma::mma_sync(c, a, bf, c);
        }
        #pragma unroll
        for (int q = 0; q < c.num_elements; q++){
            float v = c.x[q];
            #pragma unroll
            for (int k=0;k<15;k++)
                cnt[k] += (v >= th[k]) ? 1.0f : 0.0f;
        }
    }

    #pragma unroll
    for (int off=16; off; off>>=1)
        #pragma unroll
        for (int k=0;k<15;k++)
            cnt[k] += __shfl_down_sync(0xffffffffu, cnt[k], off);
    if ((threadIdx.x & 31) == 0)
        #pragma unroll
        for (int k=0;k<15;k++)
            atomicAdd(&scnt[k], cnt[k]);
    __syncthreads();
    if (threadIdx.x < 15)
        atomicAdd(&g_hist[b*NBINS + threadIdx.x + 1], scnt[threadIdx.x]);
}

// ---------------- attention pooling (both sides fused) ----------------------
__global__ void __launch_bounds__(256) k_att1(const float* __restrict__ attW){
    int side = blockIdx.y;
    const float* af = side ? g_af2  : g_af1;
    float* ctx      = side ? g_ctx2 : g_ctx1;
    int b = blockIdx.x;
    __shared__ float sm[8*32], smean[32];
    int f = threadIdx.x & 31, grp = threadIdx.x >> 5;
    const float* base = af + (size_t)b*NPG*32;
    float acc = 0.f;
    for (int n = grp; n < NPG; n += 8) acc += base[n*32 + f];
    sm[grp*32 + f] = acc;
    __syncthreads();
    if (threadIdx.x < 32){
        float m = 0.f;
        for (int g=0; g<8; g++) m += sm[g*32 + threadIdx.x];
        smean[threadIdx.x] = m * (1.0f/512.0f);
    }
    __syncthreads();
    if (threadIdx.x < 32){
        int j = threadIdx.x;
        float t = 0.f;
        for (int ff=0; ff<32; ff++) t += smean[ff]*attW[ff*32 + j];
        ctx[b*32 + j] = tanhf(t);
    }
}

__global__ void __launch_bounds__(256) k_att2(){
    int side = blockIdx.y;
    const float* af  = side ? g_af2  : g_af1;
    const float* ctx = side ? g_ctx2 : g_ctx1;
    float* gp        = side ? g_p2   : g_p1;
    int b = blockIdx.x;
    __shared__ float st[32];
    __shared__ float ssig[NPG];
    __shared__ float sm[8*32];
    if (threadIdx.x < 32) st[threadIdx.x] = ctx[b*32 + threadIdx.x];
    __syncthreads();
    const float* base = af + (size_t)b*NPG*32;
    for (int n = threadIdx.x; n < NPG; n += 256){
        float d = 0.f;
        #pragma unroll
        for (int q=0; q<8; q++){
            float4 v = *(const float4*)(base + n*32 + q*4);
            d += v.x*st[q*4] + v.y*st[q*4+1] + v.z*st[q*4+2] + v.w*st[q*4+3];
        }
        ssig[n] = 1.0f/(1.0f + __expf(-d));
    }
    __syncthreads();
    int f = threadIdx.x & 31, grp = threadIdx.x >> 5;
    float acc = 0.f;
    for (int n = grp; n < NPG; n += 8) acc += base[n*32 + f] * ssig[n];
    sm[grp*32 + f] = acc;
    __syncthreads();
    if (threadIdx.x < 32){
        float s = 0.f;
        for (int g=0; g<8; g++) s += sm[g*32 + threadIdx.x];
        gp[b*32 + threadIdx.x] = s;
    }
}

// ---------------- NTN + head -----------------------------------------------
__global__ void __launch_bounds__(512) k_ntn(const float* __restrict__ ntnW,
                                             const float* __restrict__ ntnV,
                                             const float* __restrict__ ntnb,
                                             const float* __restrict__ fc1W,
                                             const float* __restrict__ fc1b,
                                             const float* __restrict__ scW,
                                             const float* __restrict__ scb,
                                             float* __restrict__ out){
    int b = blockIdx.x;
    __shared__ float sp1[32], sp2[32], sred[512], sfeat[32], sh[16];
    int tid = threadIdx.x;
    if (tid < 32){ sp1[tid] = g_p1[b*32+tid]; sp2[tid] = g_p2[b*32+tid]; }
    __syncthreads();
    int j = tid >> 4, k = tid & 15;
    float acc = 0.f;
    #pragma unroll 8
    for (int i=0; i<32; i++) acc += sp1[i] * ntnW[i*512 + j*16 + k];
    sred[tid] = acc * sp2[j];
    __syncthreads();
    for (int off=256; off>=16; off>>=1){
        if (tid < off) sred[tid] += sred[tid+off];
        __syncthreads();
    }
    if (tid < 16){
        float blk = 0.f;
        for (int i=0; i<32; i++)
            blk += sp1[i]*ntnV[tid*64 + i] + sp2[i]*ntnV[tid*64 + 32 + i];
        sfeat[tid] = fmaxf(sred[tid] + blk + ntnb[tid], 0.f);
        float ck  = (tid==0)  ? 262144.0f : g_hist[b*NBINS + tid];
        float ck1 = (tid==15) ? 0.0f      : g_hist[b*NBINS + tid + 1];
        sfeat[16 + tid] = (ck - ck1) * (1.0f/262144.0f);
    }
    __syncthreads();
    if (tid < 16){
        float h = fc1b[tid];
        for (int m=0; m<32; m++) h += sfeat[m]*fc1W[m*16 + tid];
        sh[tid] = fmaxf(h, 0.f);
    }
    __syncthreads();
    if (tid == 0){
        float o = scb[0];
        for (int n=0; n<16; n++) o += sh[n]*scW[n];
        out[b] = 1.0f/(1.0f + expf(-o));
    }
}

// ---------------- launch ----------------------------------------------------
extern "C" void kernel_launch(void* const* d_in, const int* in_sizes, int n_in,
                              void* d_out, int out_size) {
    const float* x1   = (const float*)d_in[0];
    const float* x2   = (const float*)d_in[1];
    const int*   ei1  = (const int*)d_in[2];
    const int*   ei2  = (const int*)d_in[3];
    const float* W1   = (const float*)d_in[6];
    const float* b1   = (const float*)d_in[7];
    const float* W2   = (const float*)d_in[8];
    const float* b2   = (const float*)d_in[9];
    const float* W3   = (const float*)d_in[10];
    const float* b3   = (const float*)d_in[11];
    const float* attW = (const float*)d_in[12];
    const float* ntnW = (const float*)d_in[13];
    const float* ntnV = (const float*)d_in[14];
    const float* ntnb = (const float*)d_in[15];
    const float* fc1W = (const float*)d_in[16];
    const float* fc1b = (const float*)d_in[17];
    const float* scW  = (const float*)d_in[18];
    const float* scb  = (const float*)d_in[19];
    float* out = (float*)d_out;
    int E = in_sizes[2] / 2;

    // CSR build, both sides fused (k_count also inits histogram state)
    k_count<<<dim3((E+255)/256, 2), 256>>>(ei1, ei2, E);
    k_scan1<<<dim3(256, 2), 256>>>();
    k_scan2<<<2, 256>>>();
    k_scan3<<<dim3(TOT/256, 2), 256>>>(E);
    k_fill<<<dim3((E+255)/256, 2), 256>>>(ei1, ei2, E);

    // GCN stack, both sides fused (h0 in fp16)
    k_gemm<128,64><<<dim3(TOT/32, 2), 256>>>(x1, x2, W1, 0);
    k_gf<64,true,false><<<dim3(TOT*8/256, 2), 256>>>(b1);

    k_gemm<64,64><<<dim3(TOT/32, 2), 256>>>(nullptr, nullptr, W2, 1);
    k_gf<64,true,false><<<dim3(TOT*8/256, 2), 256>>>(b2);

    k_gemm<64,32><<<dim3(TOT/64, 2), 256>>>(nullptr, nullptr, W3, 1);
    k_gf<32,false,true><<<dim3(TOT*4/256, 2), 256>>>(b3);

    // histogram chain (thresholds computed inside dotB)
    k_dotA<<<BGR*16, 256>>>();
    k_dotB<<<BGR*16, 256>>>();

    // attention, both sides fused
    k_att1<<<dim3(BGR, 2), 256>>>(attW);
    k_att2<<<dim3(BGR, 2), 256>>>();

    k_ntn<<<BGR, 512>>>(ntnW, ntnV, ntnb, fc1W, fc1b, scW, scb, out);
}